// round 1
// baseline (speedup 1.0000x reference)
#include <cuda_runtime.h>
#include <cstdint>

#define NN      500000
#define NE      8000000
#define NG      16384
#define INF     74
#define HID     64
#define CH      128

// ---------------- scratch (device globals; no allocation) ----------------
__device__ float g_P  [(size_t)NN * HID];   // h @ gW  (pre-aggregation)
__device__ float g_R  [(size_t)NN * HID];   // relu(h @ rW + rb)
__device__ float g_AGG[(size_t)NN * HID];   // edge-aggregated P
__device__ float g_H  [(size_t)NN * HID];   // layer output (ping buffer)
__device__ float g_GF [(size_t)NG * HID];   // pooled graph features
__device__ float g_HID[(size_t)NG * CH];    // classifier hidden

// ---------------- helpers ----------------
__device__ __forceinline__ void red4(float* p, float4 v) {
    asm volatile("red.global.add.v4.f32 [%0], {%1,%2,%3,%4};"
                 :: "l"(p), "f"(v.x), "f"(v.y), "f"(v.z), "f"(v.w)
                 : "memory");
}

__global__ void zero_kernel(float* __restrict__ buf, unsigned n4) {
    unsigned i = blockIdx.x * blockDim.x + threadIdx.x;
    if (i < n4) reinterpret_cast<float4*>(buf)[i] = make_float4(0.f, 0.f, 0.f, 0.f);
}

// ---------------- fused dual GEMM: P = h@gW ; R = relu(h@rW + rb) ----------------
// Block tile: 32 rows x 128 cols (cols 0..63 -> P, 64..127 -> R), 256 threads,
// micro-tile 4 rows x 4 cols per thread. Full K in one smem stage (K <= 74).
template <int D_IN, bool FROM_PARAM>
__global__ void gemm_dual(const float* __restrict__ hin,
                          const float* __restrict__ gW,
                          const float* __restrict__ rW,
                          const float* __restrict__ rb) {
    __shared__ float As[32][D_IN];     // A tile, row-major
    __shared__ float Ws[D_IN][128];    // [gW | rW]

    const float* h = FROM_PARAM ? hin : g_H;
    const int t = threadIdx.x;
    const int rowBase = blockIdx.x * 32;

    // load A tile (coalesced-ish scalar loads)
    for (int i = t; i < 32 * D_IN; i += 256) {
        int r = i / D_IN, k = i - r * D_IN;
        As[r][k] = h[(size_t)(rowBase + r) * D_IN + k];
    }
    // load combined weights
    for (int i = t; i < D_IN * 64; i += 256) {
        int k = i >> 6, c = i & 63;
        Ws[k][c]      = gW[i];
        Ws[k][64 + c] = rW[i];
    }
    __syncthreads();

    const int tx = t & 31;        // column group (4 cols)
    const int ty = t >> 5;        // row group (4 rows)
    const int c0 = tx * 4;

    float acc[4][4];
#pragma unroll
    for (int i = 0; i < 4; i++)
#pragma unroll
        for (int j = 0; j < 4; j++) acc[i][j] = 0.f;

#pragma unroll 2
    for (int k = 0; k < D_IN; k++) {
        float4 b = *reinterpret_cast<const float4*>(&Ws[k][c0]);
#pragma unroll
        for (int i = 0; i < 4; i++) {
            float a = As[ty * 4 + i][k];     // broadcast within warp
            acc[i][0] += a * b.x;
            acc[i][1] += a * b.y;
            acc[i][2] += a * b.z;
            acc[i][3] += a * b.w;
        }
    }

    const bool isR = (c0 >= 64);
    const int col = isR ? (c0 - 64) : c0;
    float4 bias = make_float4(0.f, 0.f, 0.f, 0.f);
    if (isR) bias = *reinterpret_cast<const float4*>(&rb[col]);

#pragma unroll
    for (int i = 0; i < 4; i++) {
        size_t off = (size_t)(rowBase + ty * 4 + i) * 64 + col;
        float4 v = make_float4(acc[i][0], acc[i][1], acc[i][2], acc[i][3]);
        if (isR) {
            v.x = fmaxf(v.x + bias.x, 0.f);
            v.y = fmaxf(v.y + bias.y, 0.f);
            v.z = fmaxf(v.z + bias.z, 0.f);
            v.w = fmaxf(v.w + bias.w, 0.f);
            *reinterpret_cast<float4*>(&g_R[off]) = v;
        } else {
            *reinterpret_cast<float4*>(&g_P[off]) = v;
        }
    }
}

// ---------------- edge scatter-add: AGG[dst] += P[src], d = 64 ----------------
// 8 threads per edge, each handles 8 floats (two float4 REDs).
__global__ void edge_agg(const int* __restrict__ src, const int* __restrict__ dst) {
    unsigned tid = blockIdx.x * 256u + threadIdx.x;
    unsigned e = tid >> 3;
    if (e >= NE) return;
    int c = (tid & 7) << 3;
    size_t so = (size_t)src[e] * 64 + c;
    size_t dofs = (size_t)dst[e] * 64 + c;
    float4 v0 = *reinterpret_cast<const float4*>(&g_P[so]);
    float4 v1 = *reinterpret_cast<const float4*>(&g_P[so + 4]);
    red4(&g_AGG[dofs], v0);
    red4(&g_AGG[dofs + 4], v1);
}

// ---------------- post: H = relu(AGG + gb) + R ----------------
__global__ void post_kernel(const float* __restrict__ gb) {
    unsigned i = blockIdx.x * 256u + threadIdx.x;   // over NN*16 float4s
    if (i >= NN * 16u) return;
    int c = (i & 15) * 4;
    size_t off = (size_t)i * 4;
    float4 a = *reinterpret_cast<const float4*>(&g_AGG[off]);
    float4 b = *reinterpret_cast<const float4*>(&gb[c]);
    float4 r = *reinterpret_cast<const float4*>(&g_R[off]);
    float4 o;
    o.x = fmaxf(a.x + b.x, 0.f) + r.x;
    o.y = fmaxf(a.y + b.y, 0.f) + r.y;
    o.z = fmaxf(a.z + b.z, 0.f) + r.z;
    o.w = fmaxf(a.w + b.w, 0.f) + r.w;
    *reinterpret_cast<float4*>(&g_H[off]) = o;
}

// ---------------- sum pooling: GF[gid[n]] += H[n] ----------------
__global__ void pool_kernel(const int* __restrict__ gid) {
    unsigned tid = blockIdx.x * 256u + threadIdx.x;   // NN*8 threads
    unsigned n = tid >> 3;
    if (n >= NN) return;
    int c = (tid & 7) << 3;
    int g = gid[n];
    size_t so = (size_t)n * 64 + c;
    float4 v0 = *reinterpret_cast<const float4*>(&g_H[so]);
    float4 v1 = *reinterpret_cast<const float4*>(&g_H[so + 4]);
    size_t dofs = (size_t)g * 64 + c;
    red4(&g_GF[dofs], v0);
    red4(&g_GF[dofs + 4], v1);
}

// ---------------- classifier MLP ----------------
__global__ void mlp1_kernel(const float* __restrict__ cW1, const float* __restrict__ cb1) {
    __shared__ float W[64 * 128];
    int t = threadIdx.x;
    for (int i = t; i < 64 * 128; i += 256) W[i] = cW1[i];
    __syncthreads();
    int oc = t & 127;
    int g = blockIdx.x * 2 + (t >> 7);
    float s = cb1[oc];
    const float* gf = &g_GF[(size_t)g * 64];
#pragma unroll 8
    for (int k = 0; k < 64; k++) s += gf[k] * W[k * 128 + oc];
    g_HID[(size_t)g * 128 + oc] = fmaxf(s, 0.f);
}

__global__ void mlp2_kernel(const float* __restrict__ cW2, const float* __restrict__ cb2,
                            float* __restrict__ out) {
    __shared__ float W[128 * 2];
    int t = threadIdx.x;
    if (t < 256) W[t] = cW2[t];
    __syncthreads();
    unsigned tid = blockIdx.x * 256u + threadIdx.x;
    unsigned g = tid >> 1;
    int cls = tid & 1;
    if (g >= NG) return;
    float s = cb2[cls];
    const float* hd = &g_HID[(size_t)g * 128];
#pragma unroll 8
    for (int k = 0; k < 128; k++) s += hd[k] * W[k * 2 + cls];
    out[g * 2 + cls] = s;
}

// ---------------- launch ----------------
extern "C" void kernel_launch(void* const* d_in, const int* in_sizes, int n_in,
                              void* d_out, int out_size) {
    const float* node_feats = (const float*)d_in[0];
    const int*   src        = (const int*)d_in[1];
    const int*   dst        = (const int*)d_in[2];
    const int*   gid        = (const int*)d_in[3];
    const float* gW[3] = {(const float*)d_in[4],  (const float*)d_in[8],  (const float*)d_in[12]};
    const float* gb[3] = {(const float*)d_in[5],  (const float*)d_in[9],  (const float*)d_in[13]};
    const float* rW[3] = {(const float*)d_in[6],  (const float*)d_in[10], (const float*)d_in[14]};
    const float* rb[3] = {(const float*)d_in[7],  (const float*)d_in[11], (const float*)d_in[15]};
    const float* cW1 = (const float*)d_in[16];
    const float* cb1 = (const float*)d_in[17];
    const float* cW2 = (const float*)d_in[18];
    const float* cb2 = (const float*)d_in[19];
    float* out = (float*)d_out;

    float* aggp; cudaGetSymbolAddress((void**)&aggp, g_AGG);
    float* gfp;  cudaGetSymbolAddress((void**)&gfp,  g_GF);

    const int GEMM_BLOCKS = NN / 32;          // 15625
    const int EDGE_BLOCKS = (NE * 8) / 256;   // 250000
    const int POST_BLOCKS = (NN * 16) / 256;  // 31250
    const int POOL_BLOCKS = (NN * 8) / 256;   // 15625
    const int ZAGG_BLOCKS = (NN * 16) / 256;  // 31250  (NN*64/4 float4s)
    const int ZGF_BLOCKS  = (NG * 16) / 256;  // 1024

    // ---- layer 0 (input 74-dim) ----
    gemm_dual<INF, true><<<GEMM_BLOCKS, 256>>>(node_feats, gW[0], rW[0], rb[0]);
    zero_kernel<<<ZAGG_BLOCKS, 256>>>(aggp, NN * 16u);
    edge_agg<<<EDGE_BLOCKS, 256>>>(src, dst);
    post_kernel<<<POST_BLOCKS, 256>>>(gb[0]);

    // ---- layers 1, 2 (64-dim, input = g_H) ----
    for (int l = 1; l <= 2; l++) {
        gemm_dual<HID, false><<<GEMM_BLOCKS, 256>>>(nullptr, gW[l], rW[l], rb[l]);
        zero_kernel<<<ZAGG_BLOCKS, 256>>>(aggp, NN * 16u);
        edge_agg<<<EDGE_BLOCKS, 256>>>(src, dst);
        post_kernel<<<POST_BLOCKS, 256>>>(gb[l]);
    }

    // ---- readout + classifier ----
    zero_kernel<<<ZGF_BLOCKS, 256>>>(gfp, NG * 16u);
    pool_kernel<<<POOL_BLOCKS, 256>>>(gid);
    mlp1_kernel<<<NG / 2, 256>>>(cW1, cb1);
    mlp2_kernel<<<(NG * 2) / 256, 256>>>(cW2, cb2, out);
}

// round 2
// speedup vs baseline: 1.7800x; 1.7800x over previous
#include <cuda_runtime.h>
#include <cstdint>

#define NN      500000
#define NE      8000000
#define NG      16384
#define INF     74
#define HID     64
#define CH      128
#define NB      489          // ceil(NN/1024) for the scan

// ---------------- scratch (device globals; no allocation) ----------------
__device__ float g_P  [(size_t)NN * HID];   // h @ gW  (pre-aggregation)
__device__ float g_R  [(size_t)NN * HID];   // relu(h @ rW + rb)
__device__ float g_AGG[(size_t)NN * HID];   // aggregated P per node
__device__ float g_GF [(size_t)NG * HID];   // pooled graph features
__device__ float g_HID[(size_t)NG * CH];    // classifier hidden

// CSR build scratch
__device__ int g_cnt [NN];
__device__ int g_off [NN + 1];
__device__ int g_cur [NN];
__device__ int g_bsum [512];
__device__ int g_bsumX[512];
__device__ int g_esrc[NE];                  // src ids grouped by dst

// ---------------- helpers ----------------
__device__ __forceinline__ void red4(float* p, float4 v) {
    asm volatile("red.global.add.v4.f32 [%0], {%1,%2,%3,%4};"
                 :: "l"(p), "f"(v.x), "f"(v.y), "f"(v.z), "f"(v.w)
                 : "memory");
}

__global__ void zero_kernel(float* __restrict__ buf, unsigned n4) {
    unsigned i = blockIdx.x * blockDim.x + threadIdx.x;
    if (i < n4) reinterpret_cast<float4*>(buf)[i] = make_float4(0.f, 0.f, 0.f, 0.f);
}

__global__ void zero_cnt_kernel() {
    unsigned i = blockIdx.x * 256u + threadIdx.x;
    if (i < NN) g_cnt[i] = 0;
}

// ---------------- CSR build: hist -> scan -> scatter ----------------
__global__ void hist_kernel(const int* __restrict__ dst) {
    unsigned e = blockIdx.x * 256u + threadIdx.x;
    if (e < NE) atomicAdd(&g_cnt[dst[e]], 1);
}

// per-block exclusive scan over 1024 counts (256 thr x 4)
__global__ void scan1_kernel() {
    __shared__ int sm[256];
    int b = blockIdx.x, t = threadIdx.x;
    int base = b * 1024 + t * 4;
    int v[4];
#pragma unroll
    for (int i = 0; i < 4; i++) {
        int idx = base + i;
        v[i] = (idx < NN) ? g_cnt[idx] : 0;
    }
    int s = v[0] + v[1] + v[2] + v[3];
    sm[t] = s;
    __syncthreads();
    for (int d = 1; d < 256; d <<= 1) {
        int x = (t >= d) ? sm[t - d] : 0;
        __syncthreads();
        sm[t] += x;
        __syncthreads();
    }
    int excl = sm[t] - s;
    if (t == 255) g_bsum[b] = sm[255];
    int run = excl;
#pragma unroll
    for (int i = 0; i < 4; i++) {
        int idx = base + i;
        if (idx < NN) g_off[idx] = run;
        run += v[i];
    }
}

__global__ void scan2_kernel() {    // 1 block, 512 threads
    __shared__ int sm[512];
    int t = threadIdx.x;
    int v = (t < NB) ? g_bsum[t] : 0;
    sm[t] = v;
    __syncthreads();
    for (int d = 1; d < 512; d <<= 1) {
        int x = (t >= d) ? sm[t - d] : 0;
        __syncthreads();
        sm[t] += x;
        __syncthreads();
    }
    if (t < NB) g_bsumX[t] = sm[t] - v;
    if (t == 511) g_off[NN] = sm[511];   // == NE
}

__global__ void scan3_kernel() {
    int add = g_bsumX[blockIdx.x];
    int base = blockIdx.x * 1024 + threadIdx.x * 4;
#pragma unroll
    for (int i = 0; i < 4; i++) {
        int idx = base + i;
        if (idx < NN) {
            int o = g_off[idx] + add;
            g_off[idx] = o;
            g_cur[idx] = o;
        }
    }
}

__global__ void scatter_kernel(const int* __restrict__ src, const int* __restrict__ dst) {
    unsigned e = blockIdx.x * 256u + threadIdx.x;
    if (e >= NE) return;
    int d = dst[e];
    int pos = atomicAdd(&g_cur[d], 1);
    g_esrc[pos] = src[e];
}

// ---------------- fused dual GEMM ----------------
// A-tile 32 rows; 128 threads; micro-tile 8 rows x 4 cols; 128 output cols
// (cols 0..63 -> P = A@gW, cols 64..127 -> R = relu(A@rW + rb)).
// For !FIRST, A = relu(AGG + gbPrev) + R  computed on the fly (H never stored).
template <int D_IN, bool FIRST>
__global__ void __launch_bounds__(128) gemm_fused(
        const float* __restrict__ hin,
        const float* __restrict__ gW,
        const float* __restrict__ rW,
        const float* __restrict__ rb,
        const float* __restrict__ gbPrev) {
    __shared__ float As[32][D_IN];
    __shared__ float Ws[D_IN][128];

    const int t = threadIdx.x;
    const int rowBase = blockIdx.x * 32;

    if (FIRST) {
        for (int i = t; i < 32 * D_IN; i += 128) {
            int r = i / D_IN, k = i - r * D_IN;
            As[r][k] = hin[(size_t)(rowBase + r) * D_IN + k];
        }
    } else {
        // D_IN == 64: reconstruct H = relu(AGG + gbPrev) + R
        for (int i = t; i < 32 * 16; i += 128) {
            int r = i >> 4, k4 = (i & 15);
            size_t off = (size_t)(rowBase + r) * 64 + k4 * 4;
            float4 a  = *reinterpret_cast<const float4*>(&g_AGG[off]);
            float4 rr = *reinterpret_cast<const float4*>(&g_R[off]);
            float4 b  = *reinterpret_cast<const float4*>(&gbPrev[k4 * 4]);
            As[r][k4 * 4 + 0] = fmaxf(a.x + b.x, 0.f) + rr.x;
            As[r][k4 * 4 + 1] = fmaxf(a.y + b.y, 0.f) + rr.y;
            As[r][k4 * 4 + 2] = fmaxf(a.z + b.z, 0.f) + rr.z;
            As[r][k4 * 4 + 3] = fmaxf(a.w + b.w, 0.f) + rr.w;
        }
    }
    for (int i = t; i < D_IN * 16; i += 128) {
        int k = i >> 4, c4 = (i & 15) * 4;
        float4 g  = *reinterpret_cast<const float4*>(&gW[k * 64 + c4]);
        float4 r2 = *reinterpret_cast<const float4*>(&rW[k * 64 + c4]);
        *reinterpret_cast<float4*>(&Ws[k][c4])      = g;
        *reinterpret_cast<float4*>(&Ws[k][64 + c4]) = r2;
    }
    __syncthreads();

    const int tx = t & 31;       // 32 column groups of 4
    const int ty = t >> 5;       // 4 row groups of 8
    const int c0 = tx * 4;

    float acc[8][4];
#pragma unroll
    for (int i = 0; i < 8; i++)
#pragma unroll
        for (int j = 0; j < 4; j++) acc[i][j] = 0.f;

#pragma unroll 2
    for (int k = 0; k < D_IN; k++) {
        float4 b = *reinterpret_cast<const float4*>(&Ws[k][c0]);
#pragma unroll
        for (int i = 0; i < 8; i++) {
            float a = As[ty * 8 + i][k];    // warp-uniform broadcast
            acc[i][0] += a * b.x;
            acc[i][1] += a * b.y;
            acc[i][2] += a * b.z;
            acc[i][3] += a * b.w;
        }
    }

    const bool isR = (c0 >= 64);
    const int col = isR ? (c0 - 64) : c0;
    float4 bias = make_float4(0.f, 0.f, 0.f, 0.f);
    if (isR) bias = *reinterpret_cast<const float4*>(&rb[col]);

#pragma unroll
    for (int i = 0; i < 8; i++) {
        size_t off = (size_t)(rowBase + ty * 8 + i) * 64 + col;
        float4 v = make_float4(acc[i][0], acc[i][1], acc[i][2], acc[i][3]);
        if (isR) {
            v.x = fmaxf(v.x + bias.x, 0.f);
            v.y = fmaxf(v.y + bias.y, 0.f);
            v.z = fmaxf(v.z + bias.z, 0.f);
            v.w = fmaxf(v.w + bias.w, 0.f);
            *reinterpret_cast<float4*>(&g_R[off]) = v;
        } else {
            *reinterpret_cast<float4*>(&g_P[off]) = v;
        }
    }
}

// ---------------- CSR gather aggregation: AGG[n] = sum_{e: dst=n} P[src_e] ----------------
// one node per 16-lane half-warp, 4 floats per lane, register accumulation, no atomics
__global__ void agg_gather() {
    unsigned tid = blockIdx.x * 256u + threadIdx.x;
    unsigned n = tid >> 4;
    if (n >= NN) return;
    int lane = tid & 15;
    int beg = g_off[n], end = g_off[n + 1];
    const float4* __restrict__ P4 = reinterpret_cast<const float4*>(g_P);
    float4 acc = make_float4(0.f, 0.f, 0.f, 0.f);
    int j = beg;
    for (; j + 3 < end; j += 4) {
        int s0 = __ldg(&g_esrc[j]);
        int s1 = __ldg(&g_esrc[j + 1]);
        int s2 = __ldg(&g_esrc[j + 2]);
        int s3 = __ldg(&g_esrc[j + 3]);
        float4 v0 = __ldg(&P4[(size_t)s0 * 16 + lane]);
        float4 v1 = __ldg(&P4[(size_t)s1 * 16 + lane]);
        float4 v2 = __ldg(&P4[(size_t)s2 * 16 + lane]);
        float4 v3 = __ldg(&P4[(size_t)s3 * 16 + lane]);
        acc.x += v0.x; acc.y += v0.y; acc.z += v0.z; acc.w += v0.w;
        acc.x += v1.x; acc.y += v1.y; acc.z += v1.z; acc.w += v1.w;
        acc.x += v2.x; acc.y += v2.y; acc.z += v2.z; acc.w += v2.w;
        acc.x += v3.x; acc.y += v3.y; acc.z += v3.z; acc.w += v3.w;
    }
    for (; j < end; j++) {
        int s = __ldg(&g_esrc[j]);
        float4 v = __ldg(&P4[(size_t)s * 16 + lane]);
        acc.x += v.x; acc.y += v.y; acc.z += v.z; acc.w += v.w;
    }
    reinterpret_cast<float4*>(g_AGG)[(size_t)n * 16 + lane] = acc;
}

// ---------------- pool with fused post: GF[gid[n]] += relu(AGG[n]+gb)+R[n] ----------------
__global__ void pool_fused(const int* __restrict__ gid, const float* __restrict__ gb) {
    unsigned tid = blockIdx.x * 256u + threadIdx.x;   // NN*8 threads
    unsigned n = tid >> 3;
    if (n >= NN) return;
    int c = (tid & 7) << 3;
    int g = gid[n];
    size_t off = (size_t)n * 64 + c;
    float4 a0 = *reinterpret_cast<const float4*>(&g_AGG[off]);
    float4 a1 = *reinterpret_cast<const float4*>(&g_AGG[off + 4]);
    float4 r0 = *reinterpret_cast<const float4*>(&g_R[off]);
    float4 r1 = *reinterpret_cast<const float4*>(&g_R[off + 4]);
    float4 b0 = *reinterpret_cast<const float4*>(&gb[c]);
    float4 b1 = *reinterpret_cast<const float4*>(&gb[c + 4]);
    float4 h0, h1;
    h0.x = fmaxf(a0.x + b0.x, 0.f) + r0.x;
    h0.y = fmaxf(a0.y + b0.y, 0.f) + r0.y;
    h0.z = fmaxf(a0.z + b0.z, 0.f) + r0.z;
    h0.w = fmaxf(a0.w + b0.w, 0.f) + r0.w;
    h1.x = fmaxf(a1.x + b1.x, 0.f) + r1.x;
    h1.y = fmaxf(a1.y + b1.y, 0.f) + r1.y;
    h1.z = fmaxf(a1.z + b1.z, 0.f) + r1.z;
    h1.w = fmaxf(a1.w + b1.w, 0.f) + r1.w;
    size_t dofs = (size_t)g * 64 + c;
    red4(&g_GF[dofs], h0);
    red4(&g_GF[dofs + 4], h1);
}

// ---------------- classifier MLP ----------------
__global__ void mlp1_kernel(const float* __restrict__ cW1, const float* __restrict__ cb1) {
    __shared__ float W[64 * 128];
    int t = threadIdx.x;
    for (int i = t; i < 64 * 128; i += 256) W[i] = cW1[i];
    __syncthreads();
    int oc = t & 127;
    int g = blockIdx.x * 2 + (t >> 7);
    float s = __ldg(&cb1[oc]);
    const float* gf = &g_GF[(size_t)g * 64];
#pragma unroll 8
    for (int k = 0; k < 64; k++) s += gf[k] * W[k * 128 + oc];
    g_HID[(size_t)g * 128 + oc] = fmaxf(s, 0.f);
}

__global__ void mlp2_kernel(const float* __restrict__ cW2, const float* __restrict__ cb2,
                            float* __restrict__ out) {
    __shared__ float W[128 * 2];
    int t = threadIdx.x;
    if (t < 256) W[t] = cW2[t];
    __syncthreads();
    unsigned tid = blockIdx.x * 256u + threadIdx.x;
    unsigned g = tid >> 1;
    int cls = tid & 1;
    if (g >= NG) return;
    float s = __ldg(&cb2[cls]);
    const float* hd = &g_HID[(size_t)g * 128];
#pragma unroll 8
    for (int k = 0; k < 128; k++) s += hd[k] * W[k * 2 + cls];
    out[g * 2 + cls] = s;
}

// ---------------- launch ----------------
extern "C" void kernel_launch(void* const* d_in, const int* in_sizes, int n_in,
                              void* d_out, int out_size) {
    const float* node_feats = (const float*)d_in[0];
    const int*   src        = (const int*)d_in[1];
    const int*   dst        = (const int*)d_in[2];
    const int*   gid        = (const int*)d_in[3];
    const float* gW[3] = {(const float*)d_in[4],  (const float*)d_in[8],  (const float*)d_in[12]};
    const float* gb[3] = {(const float*)d_in[5],  (const float*)d_in[9],  (const float*)d_in[13]};
    const float* rW[3] = {(const float*)d_in[6],  (const float*)d_in[10], (const float*)d_in[14]};
    const float* rb[3] = {(const float*)d_in[7],  (const float*)d_in[11], (const float*)d_in[15]};
    const float* cW1 = (const float*)d_in[16];
    const float* cb1 = (const float*)d_in[17];
    const float* cW2 = (const float*)d_in[18];
    const float* cb2 = (const float*)d_in[19];
    float* out = (float*)d_out;

    float* gfp; cudaGetSymbolAddress((void**)&gfp, g_GF);

    const int EDGE_BLOCKS = (NE + 255) / 256;   // 31250
    const int GEMM_BLOCKS = NN / 32;            // 15625
    const int AGG_BLOCKS  = (NN * 16) / 256;    // 31250
    const int POOL_BLOCKS = (NN * 8) / 256;     // 15625
    const int ZCNT_BLOCKS = (NN + 255) / 256;   // 1954
    const int ZGF_BLOCKS  = (NG * 16) / 256;    // 1024

    // ---- CSR build (once; reused by all 3 layers) ----
    zero_cnt_kernel<<<ZCNT_BLOCKS, 256>>>();
    hist_kernel<<<EDGE_BLOCKS, 256>>>(dst);
    scan1_kernel<<<NB, 256>>>();
    scan2_kernel<<<1, 512>>>();
    scan3_kernel<<<NB, 256>>>();
    scatter_kernel<<<EDGE_BLOCKS, 256>>>(src, dst);

    // ---- layer 0 ----
    gemm_fused<INF, true><<<GEMM_BLOCKS, 128>>>(node_feats, gW[0], rW[0], rb[0], nullptr);
    agg_gather<<<AGG_BLOCKS, 256>>>();

    // ---- layer 1 ----
    gemm_fused<HID, false><<<GEMM_BLOCKS, 128>>>(nullptr, gW[1], rW[1], rb[1], gb[0]);
    agg_gather<<<AGG_BLOCKS, 256>>>();

    // ---- layer 2 ----
    gemm_fused<HID, false><<<GEMM_BLOCKS, 128>>>(nullptr, gW[2], rW[2], rb[2], gb[1]);
    agg_gather<<<AGG_BLOCKS, 256>>>();

    // ---- readout + classifier ----
    zero_kernel<<<ZGF_BLOCKS, 256>>>(gfp, NG * 16u);
    pool_fused<<<POOL_BLOCKS, 256>>>(gid, gb[2]);
    mlp1_kernel<<<NG / 2, 256>>>(cW1, cb1);
    mlp2_kernel<<<(NG * 2) / 256, 256>>>(cW2, cb2, out);
}

// round 3
// speedup vs baseline: 2.7773x; 1.5602x over previous
#include <cuda_runtime.h>
#include <cuda_fp16.h>
#include <cstdint>

#define NN      500000
#define NE      8000000
#define NG      16384
#define INF     74
#define HID     64
#define CH      128
#define NB      489          // ceil(NN/1024) for the scan

// ---------------- scratch (device globals; no allocation) ----------------
__device__ __half g_Ph [(size_t)NN * HID];  // h @ gW, fp16 (pre-aggregation)
__device__ float  g_R  [(size_t)NN * HID];  // relu(h @ rW + rb), fp32
__device__ float  g_AGG[(size_t)NN * HID];  // aggregated P per node, fp32
__device__ float  g_GF [(size_t)NG * HID];  // pooled graph features
__device__ float  g_HID[(size_t)NG * CH];   // classifier hidden

// CSR build scratch
__device__ int g_cnt [NN];
__device__ int g_off [NN + 1];
__device__ int g_cur [NN];
__device__ int g_bsum [512];
__device__ int g_bsumX[512];
__device__ int g_esrc[NE];                  // src ids grouped by dst

// ---------------- helpers ----------------
__device__ __forceinline__ void red4(float* p, float4 v) {
    asm volatile("red.global.add.v4.f32 [%0], {%1,%2,%3,%4};"
                 :: "l"(p), "f"(v.x), "f"(v.y), "f"(v.z), "f"(v.w)
                 : "memory");
}

__device__ __forceinline__ unsigned tf32r(float x) {
    unsigned u;
    asm("cvt.rna.tf32.f32 %0, %1;" : "=r"(u) : "f"(x));
    return u;
}

__device__ __forceinline__ void mma_tf32(float* d,
        unsigned a0, unsigned a1, unsigned a2, unsigned a3,
        unsigned b0, unsigned b1) {
    asm volatile(
        "mma.sync.aligned.m16n8k8.row.col.f32.tf32.tf32.f32 "
        "{%0,%1,%2,%3}, {%4,%5,%6,%7}, {%8,%9}, {%0,%1,%2,%3};"
        : "+f"(d[0]), "+f"(d[1]), "+f"(d[2]), "+f"(d[3])
        : "r"(a0), "r"(a1), "r"(a2), "r"(a3), "r"(b0), "r"(b1));
}

__global__ void zero_kernel(float* __restrict__ buf, unsigned n4) {
    unsigned i = blockIdx.x * blockDim.x + threadIdx.x;
    if (i < n4) reinterpret_cast<float4*>(buf)[i] = make_float4(0.f, 0.f, 0.f, 0.f);
}

__global__ void zero_cnt_kernel() {
    unsigned i = blockIdx.x * 256u + threadIdx.x;
    if (i < NN) g_cnt[i] = 0;
}

// ---------------- CSR build: hist -> scan -> scatter ----------------
__global__ void hist_kernel(const int* __restrict__ dst) {
    unsigned e = blockIdx.x * 256u + threadIdx.x;
    if (e < NE) atomicAdd(&g_cnt[dst[e]], 1);
}

__global__ void scan1_kernel() {
    __shared__ int sm[256];
    int b = blockIdx.x, t = threadIdx.x;
    int base = b * 1024 + t * 4;
    int v[4];
#pragma unroll
    for (int i = 0; i < 4; i++) {
        int idx = base + i;
        v[i] = (idx < NN) ? g_cnt[idx] : 0;
    }
    int s = v[0] + v[1] + v[2] + v[3];
    sm[t] = s;
    __syncthreads();
    for (int d = 1; d < 256; d <<= 1) {
        int x = (t >= d) ? sm[t - d] : 0;
        __syncthreads();
        sm[t] += x;
        __syncthreads();
    }
    int excl = sm[t] - s;
    if (t == 255) g_bsum[b] = sm[255];
    int run = excl;
#pragma unroll
    for (int i = 0; i < 4; i++) {
        int idx = base + i;
        if (idx < NN) g_off[idx] = run;
        run += v[i];
    }
}

__global__ void scan2_kernel() {    // 1 block, 512 threads
    __shared__ int sm[512];
    int t = threadIdx.x;
    int v = (t < NB) ? g_bsum[t] : 0;
    sm[t] = v;
    __syncthreads();
    for (int d = 1; d < 512; d <<= 1) {
        int x = (t >= d) ? sm[t - d] : 0;
        __syncthreads();
        sm[t] += x;
        __syncthreads();
    }
    if (t < NB) g_bsumX[t] = sm[t] - v;
    if (t == 511) g_off[NN] = sm[511];
}

__global__ void scan3_kernel() {
    int add = g_bsumX[blockIdx.x];
    int base = blockIdx.x * 1024 + threadIdx.x * 4;
#pragma unroll
    for (int i = 0; i < 4; i++) {
        int idx = base + i;
        if (idx < NN) {
            int o = g_off[idx] + add;
            g_off[idx] = o;
            g_cur[idx] = o;
        }
    }
}

__global__ void scatter_kernel(const int* __restrict__ src, const int* __restrict__ dst) {
    unsigned e = blockIdx.x * 256u + threadIdx.x;
    if (e >= NE) return;
    int d = dst[e];
    int pos = atomicAdd(&g_cur[d], 1);
    g_esrc[pos] = src[e];
}

// ---------------- fused dual GEMM on tensor cores (tf32 mma) ----------------
// Block: 256 threads (8 warps as 2 row-groups x 4 col-groups), A-tile 32 rows.
// Two passes over the same A-tile: pass0 -> P = A@gW (fp16 out),
// pass1 -> R = relu(A@rW + rb) (fp32 out). 64 output cols per pass.
// For !FIRST, A = relu(AGG + gbPrev) + R reconstructed on the fly.
template <int KP, int DIN, bool FIRST>
__global__ void __launch_bounds__(256) gemm_mma(
        const float* __restrict__ hin,
        const float* __restrict__ gW,
        const float* __restrict__ rW,
        const float* __restrict__ rb,
        const float* __restrict__ gbPrev) {
    constexpr int AST = KP + 4;                 // padded A stride (conflict-free frags)
    __shared__ unsigned As[32 * AST];
    __shared__ unsigned Ws[KP * 64];

    const int t = threadIdx.x;
    const int rowBase = blockIdx.x * 32;
    const int lane = t & 31;
    const int wid = t >> 5;
    const int g = lane >> 2;        // groupID
    const int tig = lane & 3;       // thread-in-group
    const int wr = wid >> 2;        // warp row group (0..1)
    const int wc = wid & 3;         // warp col group (0..3)
    const int r0 = wr * 16 + g;
    const int r1 = r0 + 8;

    // ---- load A tile (tf32-rounded) ----
    if (FIRST) {
        for (int i = t; i < 32 * KP; i += 256) {
            int r = i / KP, k = i - r * KP;
            float v = (k < DIN) ? hin[(size_t)(rowBase + r) * DIN + k] : 0.f;
            As[r * AST + k] = tf32r(v);
        }
    } else {
        // KP == DIN == 64: H = relu(AGG + gbPrev) + R
        for (int i = t; i < 32 * 16; i += 256) {
            int r = i >> 4, k4 = (i & 15);
            size_t off = (size_t)(rowBase + r) * 64 + k4 * 4;
            float4 a  = *reinterpret_cast<const float4*>(&g_AGG[off]);
            float4 rr = *reinterpret_cast<const float4*>(&g_R[off]);
            float4 b  = *reinterpret_cast<const float4*>(&gbPrev[k4 * 4]);
            uint4 o;
            o.x = tf32r(fmaxf(a.x + b.x, 0.f) + rr.x);
            o.y = tf32r(fmaxf(a.y + b.y, 0.f) + rr.y);
            o.z = tf32r(fmaxf(a.z + b.z, 0.f) + rr.z);
            o.w = tf32r(fmaxf(a.w + b.w, 0.f) + rr.w);
            *reinterpret_cast<uint4*>(&As[r * AST + k4 * 4]) = o;
        }
    }

    // ================= pass 0: P = A @ gW =================
    for (int i = t; i < KP * 64; i += 256) {
        int k = i >> 6, c = i & 63;
        float v = (k < DIN) ? gW[k * 64 + c] : 0.f;
        Ws[(k << 6) | (c ^ ((k & 3) << 3))] = tf32r(v);
    }
    __syncthreads();

    {
        float acc[2][4] = {{0.f,0.f,0.f,0.f},{0.f,0.f,0.f,0.f}};
#pragma unroll
        for (int ks = 0; ks < KP / 8; ks++) {
            const int kA = ks * 8 + tig;
            const int kB = kA + 4;
            unsigned a0 = As[r0 * AST + kA];
            unsigned a1 = As[r1 * AST + kA];
            unsigned a2 = As[r0 * AST + kB];
            unsigned a3 = As[r1 * AST + kB];
#pragma unroll
            for (int nt = 0; nt < 2; nt++) {
                int n = wc * 16 + nt * 8 + g;
                unsigned b0 = Ws[(kA << 6) | (n ^ ((kA & 3) << 3))];
                unsigned b1 = Ws[(kB << 6) | (n ^ ((kB & 3) << 3))];
                mma_tf32(acc[nt], a0, a1, a2, a3, b0, b1);
            }
        }
        // epilogue P -> fp16
#pragma unroll
        for (int nt = 0; nt < 2; nt++) {
            int col = wc * 16 + nt * 8 + tig * 2;
            size_t o0 = (size_t)(rowBase + r0) * 64 + col;
            size_t o1 = (size_t)(rowBase + r1) * 64 + col;
            *reinterpret_cast<__half2*>(&g_Ph[o0]) = __floats2half2_rn(acc[nt][0], acc[nt][1]);
            *reinterpret_cast<__half2*>(&g_Ph[o1]) = __floats2half2_rn(acc[nt][2], acc[nt][3]);
        }
    }
    __syncthreads();

    // ================= pass 1: R = relu(A @ rW + rb) =================
    for (int i = t; i < KP * 64; i += 256) {
        int k = i >> 6, c = i & 63;
        float v = (k < DIN) ? rW[k * 64 + c] : 0.f;
        Ws[(k << 6) | (c ^ ((k & 3) << 3))] = tf32r(v);
    }
    __syncthreads();

    {
        float acc[2][4] = {{0.f,0.f,0.f,0.f},{0.f,0.f,0.f,0.f}};
#pragma unroll
        for (int ks = 0; ks < KP / 8; ks++) {
            const int kA = ks * 8 + tig;
            const int kB = kA + 4;
            unsigned a0 = As[r0 * AST + kA];
            unsigned a1 = As[r1 * AST + kA];
            unsigned a2 = As[r0 * AST + kB];
            unsigned a3 = As[r1 * AST + kB];
#pragma unroll
            for (int nt = 0; nt < 2; nt++) {
                int n = wc * 16 + nt * 8 + g;
                unsigned b0 = Ws[(kA << 6) | (n ^ ((kA & 3) << 3))];
                unsigned b1 = Ws[(kB << 6) | (n ^ ((kB & 3) << 3))];
                mma_tf32(acc[nt], a0, a1, a2, a3, b0, b1);
            }
        }
        // epilogue R -> fp32 with bias + relu
#pragma unroll
        for (int nt = 0; nt < 2; nt++) {
            int col = wc * 16 + nt * 8 + tig * 2;
            float bx = rb[col], by = rb[col + 1];
            size_t o0 = (size_t)(rowBase + r0) * 64 + col;
            size_t o1 = (size_t)(rowBase + r1) * 64 + col;
            float2 v0 = make_float2(fmaxf(acc[nt][0] + bx, 0.f), fmaxf(acc[nt][1] + by, 0.f));
            float2 v1 = make_float2(fmaxf(acc[nt][2] + bx, 0.f), fmaxf(acc[nt][3] + by, 0.f));
            *reinterpret_cast<float2*>(&g_R[o0]) = v0;
            *reinterpret_cast<float2*>(&g_R[o1]) = v1;
        }
    }
}

// ---------------- CSR gather aggregation: AGG[n] = sum_{e: dst=n} P[src_e] ----------------
// one node per 16-lane half-warp, 4 halves per lane, fp32 register accumulation
__global__ void agg_gather() {
    unsigned tid = blockIdx.x * 256u + threadIdx.x;
    unsigned n = tid >> 4;
    if (n >= NN) return;
    int lane = tid & 15;
    int beg = g_off[n], end = g_off[n + 1];
    const uint2* __restrict__ P2 = reinterpret_cast<const uint2*>(g_Ph);
    float4 acc = make_float4(0.f, 0.f, 0.f, 0.f);
    int j = beg;
    for (; j + 3 < end; j += 4) {
        int s0 = __ldg(&g_esrc[j]);
        int s1 = __ldg(&g_esrc[j + 1]);
        int s2 = __ldg(&g_esrc[j + 2]);
        int s3 = __ldg(&g_esrc[j + 3]);
        uint2 u0 = __ldg(&P2[(size_t)s0 * 16 + lane]);
        uint2 u1 = __ldg(&P2[(size_t)s1 * 16 + lane]);
        uint2 u2 = __ldg(&P2[(size_t)s2 * 16 + lane]);
        uint2 u3 = __ldg(&P2[(size_t)s3 * 16 + lane]);
#pragma unroll
        for (int q = 0; q < 4; q++) {
            uint2 u = (q == 0) ? u0 : (q == 1) ? u1 : (q == 2) ? u2 : u3;
            float2 lo = __half22float2(*reinterpret_cast<const __half2*>(&u.x));
            float2 hi = __half22float2(*reinterpret_cast<const __half2*>(&u.y));
            acc.x += lo.x; acc.y += lo.y; acc.z += hi.x; acc.w += hi.y;
        }
    }
    for (; j < end; j++) {
        int s = __ldg(&g_esrc[j]);
        uint2 u = __ldg(&P2[(size_t)s * 16 + lane]);
        float2 lo = __half22float2(*reinterpret_cast<const __half2*>(&u.x));
        float2 hi = __half22float2(*reinterpret_cast<const __half2*>(&u.y));
        acc.x += lo.x; acc.y += lo.y; acc.z += hi.x; acc.w += hi.y;
    }
    reinterpret_cast<float4*>(g_AGG)[(size_t)n * 16 + lane] = acc;
}

// ---------------- pool with fused post: GF[gid[n]] += relu(AGG[n]+gb)+R[n] ----------------
__global__ void pool_fused(const int* __restrict__ gid, const float* __restrict__ gb) {
    unsigned tid = blockIdx.x * 256u + threadIdx.x;   // NN*8 threads
    unsigned n = tid >> 3;
    if (n >= NN) return;
    int c = (tid & 7) << 3;
    int g = gid[n];
    size_t off = (size_t)n * 64 + c;
    float4 a0 = *reinterpret_cast<const float4*>(&g_AGG[off]);
    float4 a1 = *reinterpret_cast<const float4*>(&g_AGG[off + 4]);
    float4 r0 = *reinterpret_cast<const float4*>(&g_R[off]);
    float4 r1 = *reinterpret_cast<const float4*>(&g_R[off + 4]);
    float4 b0 = *reinterpret_cast<const float4*>(&gb[c]);
    float4 b1 = *reinterpret_cast<const float4*>(&gb[c + 4]);
    float4 h0, h1;
    h0.x = fmaxf(a0.x + b0.x, 0.f) + r0.x;
    h0.y = fmaxf(a0.y + b0.y, 0.f) + r0.y;
    h0.z = fmaxf(a0.z + b0.z, 0.f) + r0.z;
    h0.w = fmaxf(a0.w + b0.w, 0.f) + r0.w;
    h1.x = fmaxf(a1.x + b1.x, 0.f) + r1.x;
    h1.y = fmaxf(a1.y + b1.y, 0.f) + r1.y;
    h1.z = fmaxf(a1.z + b1.z, 0.f) + r1.z;
    h1.w = fmaxf(a1.w + b1.w, 0.f) + r1.w;
    size_t dofs = (size_t)g * 64 + c;
    red4(&g_GF[dofs], h0);
    red4(&g_GF[dofs + 4], h1);
}

// ---------------- classifier MLP ----------------
__global__ void mlp1_kernel(const float* __restrict__ cW1, const float* __restrict__ cb1) {
    __shared__ float W[64 * 128];
    int t = threadIdx.x;
    for (int i = t; i < 64 * 128; i += 256) W[i] = cW1[i];
    __syncthreads();
    int oc = t & 127;
    int g = blockIdx.x * 2 + (t >> 7);
    float s = __ldg(&cb1[oc]);
    const float* gf = &g_GF[(size_t)g * 64];
#pragma unroll 8
    for (int k = 0; k < 64; k++) s += gf[k] * W[k * 128 + oc];
    g_HID[(size_t)g * 128 + oc] = fmaxf(s, 0.f);
}

__global__ void mlp2_kernel(const float* __restrict__ cW2, const float* __restrict__ cb2,
                            float* __restrict__ out) {
    __shared__ float W[128 * 2];
    int t = threadIdx.x;
    if (t < 256) W[t] = cW2[t];
    __syncthreads();
    unsigned tid = blockIdx.x * 256u + threadIdx.x;
    unsigned g = tid >> 1;
    int cls = tid & 1;
    if (g >= NG) return;
    float s = __ldg(&cb2[cls]);
    const float* hd = &g_HID[(size_t)g * 128];
#pragma unroll 8
    for (int k = 0; k < 128; k++) s += hd[k] * W[k * 2 + cls];
    out[g * 2 + cls] = s;
}

// ---------------- launch ----------------
extern "C" void kernel_launch(void* const* d_in, const int* in_sizes, int n_in,
                              void* d_out, int out_size) {
    const float* node_feats = (const float*)d_in[0];
    const int*   src        = (const int*)d_in[1];
    const int*   dst        = (const int*)d_in[2];
    const int*   gid        = (const int*)d_in[3];
    const float* gW[3] = {(const float*)d_in[4],  (const float*)d_in[8],  (const float*)d_in[12]};
    const float* gb[3] = {(const float*)d_in[5],  (const float*)d_in[9],  (const float*)d_in[13]};
    const float* rW[3] = {(const float*)d_in[6],  (const float*)d_in[10], (const float*)d_in[14]};
    const float* rb[3] = {(const float*)d_in[7],  (const float*)d_in[11], (const float*)d_in[15]};
    const float* cW1 = (const float*)d_in[16];
    const float* cb1 = (const float*)d_in[17];
    const float* cW2 = (const float*)d_in[18];
    const float* cb2 = (const float*)d_in[19];
    float* out = (float*)d_out;

    float* gfp; cudaGetSymbolAddress((void**)&gfp, g_GF);

    const int EDGE_BLOCKS = (NE + 255) / 256;   // 31250
    const int GEMM_BLOCKS = NN / 32;            // 15625
    const int AGG_BLOCKS  = (NN * 16) / 256;    // 31250
    const int POOL_BLOCKS = (NN * 8) / 256;     // 15625
    const int ZCNT_BLOCKS = (NN + 255) / 256;   // 1954
    const int ZGF_BLOCKS  = (NG * 16) / 256;    // 1024

    // ---- CSR build (once; reused by all 3 layers) ----
    zero_cnt_kernel<<<ZCNT_BLOCKS, 256>>>();
    hist_kernel<<<EDGE_BLOCKS, 256>>>(dst);
    scan1_kernel<<<NB, 256>>>();
    scan2_kernel<<<1, 512>>>();
    scan3_kernel<<<NB, 256>>>();
    scatter_kernel<<<EDGE_BLOCKS, 256>>>(src, dst);

    // ---- layer 0 (K padded 74 -> 80) ----
    gemm_mma<80, INF, true><<<GEMM_BLOCKS, 256>>>(node_feats, gW[0], rW[0], rb[0], nullptr);
    agg_gather<<<AGG_BLOCKS, 256>>>();

    // ---- layer 1 ----
    gemm_mma<64, HID, false><<<GEMM_BLOCKS, 256>>>(nullptr, gW[1], rW[1], rb[1], gb[0]);
    agg_gather<<<AGG_BLOCKS, 256>>>();

    // ---- layer 2 ----
    gemm_mma<64, HID, false><<<GEMM_BLOCKS, 256>>>(nullptr, gW[2], rW[2], rb[2], gb[1]);
    agg_gather<<<AGG_BLOCKS, 256>>>();

    // ---- readout + classifier ----
    zero_kernel<<<ZGF_BLOCKS, 256>>>(gfp, NG * 16u);
    pool_fused<<<POOL_BLOCKS, 256>>>(gid, gb[2]);
    mlp1_kernel<<<NG / 2, 256>>>(cW1, cb1);
    mlp2_kernel<<<(NG * 2) / 256, 256>>>(cW2, cb2, out);
}

// round 5
// speedup vs baseline: 2.8028x; 1.0092x over previous
#include <cuda_runtime.h>
#include <cuda_fp16.h>
#include <cstdint>

#define NN      500000
#define NE      8000000
#define NG      16384
#define INF     74
#define HID     64
#define CH      128
#define NB      489          // ceil(NN/1024) for the scan

// ---------------- scratch (device globals; no allocation) ----------------
__device__ __half g_Ph [(size_t)NN * HID];  // h @ gW, fp16 (pre-aggregation)
__device__ float  g_R  [(size_t)NN * HID];  // relu(h @ rW + rb), fp32
__device__ float  g_H  [(size_t)NN * HID];  // layer output H, fp32
__device__ float  g_GF [(size_t)NG * HID];  // pooled graph features
__device__ float  g_HID[(size_t)NG * CH];   // classifier hidden

// CSR build scratch
__device__ int g_cnt [NN];
__device__ int g_off [NN + 1];
__device__ int g_cur [NN];
__device__ int g_bsum [512];
__device__ int g_bsumX[512];
__device__ int g_esrc[NE];                  // src ids grouped by dst

// ---------------- side stream + events (created once; no device mem) ----------------
struct AuxRes {
    cudaStream_t s;
    cudaEvent_t eFork, eJoin;
    AuxRes() {
        cudaStreamCreate(&s);
        cudaEventCreateWithFlags(&eFork, cudaEventDisableTiming);
        cudaEventCreateWithFlags(&eJoin, cudaEventDisableTiming);
    }
};
static AuxRes g_aux;

// ---------------- helpers ----------------
__device__ __forceinline__ void red4(float* p, float4 v) {
    asm volatile("red.global.add.v4.f32 [%0], {%1,%2,%3,%4};"
                 :: "l"(p), "f"(v.x), "f"(v.y), "f"(v.z), "f"(v.w)
                 : "memory");
}

__device__ __forceinline__ unsigned tf32r(float x) {
    unsigned u;
    asm("cvt.rna.tf32.f32 %0, %1;" : "=r"(u) : "f"(x));
    return u;
}

__device__ __forceinline__ void mma_tf32(float* d,
        unsigned a0, unsigned a1, unsigned a2, unsigned a3,
        unsigned b0, unsigned b1) {
    asm volatile(
        "mma.sync.aligned.m16n8k8.row.col.f32.tf32.tf32.f32 "
        "{%0,%1,%2,%3}, {%4,%5,%6,%7}, {%8,%9}, {%0,%1,%2,%3};"
        : "+f"(d[0]), "+f"(d[1]), "+f"(d[2]), "+f"(d[3])
        : "r"(a0), "r"(a1), "r"(a2), "r"(a3), "r"(b0), "r"(b1));
}

__global__ void zero_misc_kernel(float* __restrict__ gf) {
    unsigned i = blockIdx.x * 256u + threadIdx.x;
    if (i < NN) g_cnt[i] = 0;
    if (i < NG * 16u) reinterpret_cast<float4*>(gf)[i] = make_float4(0.f, 0.f, 0.f, 0.f);
}

// ---------------- CSR build: hist -> scan -> scatter ----------------
__global__ void hist_kernel(const int* __restrict__ dst) {
    unsigned e = blockIdx.x * 256u + threadIdx.x;
    if (e < NE) atomicAdd(&g_cnt[dst[e]], 1);
}

__global__ void scan1_kernel() {
    __shared__ int sm[256];
    int b = blockIdx.x, t = threadIdx.x;
    int base = b * 1024 + t * 4;
    int v[4];
#pragma unroll
    for (int i = 0; i < 4; i++) {
        int idx = base + i;
        v[i] = (idx < NN) ? g_cnt[idx] : 0;
    }
    int s = v[0] + v[1] + v[2] + v[3];
    sm[t] = s;
    __syncthreads();
    for (int d = 1; d < 256; d <<= 1) {
        int x = (t >= d) ? sm[t - d] : 0;
        __syncthreads();
        sm[t] += x;
        __syncthreads();
    }
    int excl = sm[t] - s;
    if (t == 255) g_bsum[b] = sm[255];
    int run = excl;
#pragma unroll
    for (int i = 0; i < 4; i++) {
        int idx = base + i;
        if (idx < NN) g_off[idx] = run;
        run += v[i];
    }
}

__global__ void scan2_kernel() {    // 1 block, 512 threads
    __shared__ int sm[512];
    int t = threadIdx.x;
    int v = (t < NB) ? g_bsum[t] : 0;
    sm[t] = v;
    __syncthreads();
    for (int d = 1; d < 512; d <<= 1) {
        int x = (t >= d) ? sm[t - d] : 0;
        __syncthreads();
        sm[t] += x;
        __syncthreads();
    }
    if (t < NB) g_bsumX[t] = sm[t] - v;
    if (t == 511) g_off[NN] = sm[511];
}

__global__ void scan3_kernel() {
    int add = g_bsumX[blockIdx.x];
    int base = blockIdx.x * 1024 + threadIdx.x * 4;
#pragma unroll
    for (int i = 0; i < 4; i++) {
        int idx = base + i;
        if (idx < NN) {
            int o = g_off[idx] + add;
            g_off[idx] = o;
            g_cur[idx] = o;
        }
    }
}

__global__ void scatter_kernel(const int* __restrict__ src, const int* __restrict__ dst) {
    unsigned e = blockIdx.x * 256u + threadIdx.x;
    if (e >= NE) return;
    int d = dst[e];
    int pos = atomicAdd(&g_cur[d], 1);
    g_esrc[pos] = src[e];
}

// ---------------- layer-0 GEMM (K padded 74->80), two passes ----------------
// Block 256 threads; A-tile 32 rows; pass0: P = A@gW (fp16), pass1: R = relu(A@rW+rb).
__global__ void __launch_bounds__(256) gemm_l0(
        const float* __restrict__ hin,
        const float* __restrict__ gW,
        const float* __restrict__ rW,
        const float* __restrict__ rb) {
    constexpr int KP = 80, AST = 84;
    __shared__ unsigned As[32 * AST];
    __shared__ unsigned Ws[KP * 64];

    const int t = threadIdx.x;
    const int rowBase = blockIdx.x * 32;
    const int lane = t & 31;
    const int wid = t >> 5;
    const int g = lane >> 2;
    const int tig = lane & 3;
    const int wr = wid >> 2;
    const int wc = wid & 3;
    const int r0 = wr * 16 + g;
    const int r1 = r0 + 8;

    for (int i = t; i < 32 * KP; i += 256) {
        int r = i / KP, k = i - r * KP;
        float v = (k < INF) ? hin[(size_t)(rowBase + r) * INF + k] : 0.f;
        As[r * AST + k] = tf32r(v);
    }

    // pass 0: P = A @ gW
    for (int i = t; i < KP * 64; i += 256) {
        int k = i >> 6, c = i & 63;
        float v = (k < INF) ? gW[k * 64 + c] : 0.f;
        Ws[(k << 6) | (c ^ ((k & 3) << 3))] = tf32r(v);
    }
    __syncthreads();
    {
        float acc[2][4] = {{0.f,0.f,0.f,0.f},{0.f,0.f,0.f,0.f}};
#pragma unroll
        for (int ks = 0; ks < KP / 8; ks++) {
            const int kA = ks * 8 + tig, kB = kA + 4;
            unsigned a0 = As[r0 * AST + kA];
            unsigned a1 = As[r1 * AST + kA];
            unsigned a2 = As[r0 * AST + kB];
            unsigned a3 = As[r1 * AST + kB];
#pragma unroll
            for (int nt = 0; nt < 2; nt++) {
                int n = wc * 16 + nt * 8 + g;
                unsigned b0 = Ws[(kA << 6) | (n ^ ((kA & 3) << 3))];
                unsigned b1 = Ws[(kB << 6) | (n ^ ((kB & 3) << 3))];
                mma_tf32(acc[nt], a0, a1, a2, a3, b0, b1);
            }
        }
#pragma unroll
        for (int nt = 0; nt < 2; nt++) {
            int col = wc * 16 + nt * 8 + tig * 2;
            size_t o0 = (size_t)(rowBase + r0) * 64 + col;
            size_t o1 = (size_t)(rowBase + r1) * 64 + col;
            *reinterpret_cast<__half2*>(&g_Ph[o0]) = __floats2half2_rn(acc[nt][0], acc[nt][1]);
            *reinterpret_cast<__half2*>(&g_Ph[o1]) = __floats2half2_rn(acc[nt][2], acc[nt][3]);
        }
    }
    __syncthreads();

    // pass 1: R = relu(A @ rW + rb)
    for (int i = t; i < KP * 64; i += 256) {
        int k = i >> 6, c = i & 63;
        float v = (k < INF) ? rW[k * 64 + c] : 0.f;
        Ws[(k << 6) | (c ^ ((k & 3) << 3))] = tf32r(v);
    }
    __syncthreads();
    {
        float acc[2][4] = {{0.f,0.f,0.f,0.f},{0.f,0.f,0.f,0.f}};
#pragma unroll
        for (int ks = 0; ks < KP / 8; ks++) {
            const int kA = ks * 8 + tig, kB = kA + 4;
            unsigned a0 = As[r0 * AST + kA];
            unsigned a1 = As[r1 * AST + kA];
            unsigned a2 = As[r0 * AST + kB];
            unsigned a3 = As[r1 * AST + kB];
#pragma unroll
            for (int nt = 0; nt < 2; nt++) {
                int n = wc * 16 + nt * 8 + g;
                unsigned b0 = Ws[(kA << 6) | (n ^ ((kA & 3) << 3))];
                unsigned b1 = Ws[(kB << 6) | (n ^ ((kB & 3) << 3))];
                mma_tf32(acc[nt], a0, a1, a2, a3, b0, b1);
            }
        }
#pragma unroll
        for (int nt = 0; nt < 2; nt++) {
            int col = wc * 16 + nt * 8 + tig * 2;
            float bx = rb[col], by = rb[col + 1];
            size_t o0 = (size_t)(rowBase + r0) * 64 + col;
            size_t o1 = (size_t)(rowBase + r1) * 64 + col;
            *reinterpret_cast<float2*>(&g_R[o0]) =
                make_float2(fmaxf(acc[nt][0] + bx, 0.f), fmaxf(acc[nt][1] + by, 0.f));
            *reinterpret_cast<float2*>(&g_R[o1]) =
                make_float2(fmaxf(acc[nt][2] + bx, 0.f), fmaxf(acc[nt][3] + by, 0.f));
        }
    }
}

// ---------------- layers 1/2 GEMM: single pass, 128 output cols ----------------
// A = g_H (fp32). Cols 0..63 -> P (fp16), 64..127 -> R = relu(.+rb).
__global__ void __launch_bounds__(256) gemm64(
        const float* __restrict__ gW,
        const float* __restrict__ rW,
        const float* __restrict__ rb) {
    constexpr int AST = 68;
    __shared__ unsigned As[32 * AST];
    __shared__ unsigned Ws[64 * 128];

    const int t = threadIdx.x;
    const int rowBase = blockIdx.x * 32;
    const int lane = t & 31;
    const int wid = t >> 5;
    const int g = lane >> 2;
    const int tig = lane & 3;
    const int wr = wid >> 2;        // 0..1
    const int wc = wid & 3;         // 0..3
    const int r0 = wr * 16 + g;
    const int r1 = r0 + 8;

    for (int i = t; i < 32 * 16; i += 256) {
        int r = i >> 4, k4 = i & 15;
        float4 v = *reinterpret_cast<const float4*>(&g_H[(size_t)(rowBase + r) * 64 + k4 * 4]);
        uint4 o;
        o.x = tf32r(v.x); o.y = tf32r(v.y); o.z = tf32r(v.z); o.w = tf32r(v.w);
        *reinterpret_cast<uint4*>(&As[r * AST + k4 * 4]) = o;
    }
    for (int i = t; i < 64 * 128; i += 256) {
        int k = i >> 7, c = i & 127;
        float v = (c < 64) ? gW[k * 64 + c] : rW[k * 64 + (c - 64)];
        Ws[(k << 7) | (c ^ ((k & 3) << 3))] = tf32r(v);
    }
    __syncthreads();

    float acc[4][4];
#pragma unroll
    for (int i = 0; i < 4; i++)
#pragma unroll
        for (int j = 0; j < 4; j++) acc[i][j] = 0.f;

#pragma unroll
    for (int ks = 0; ks < 8; ks++) {
        const int kA = ks * 8 + tig, kB = kA + 4;
        unsigned a0 = As[r0 * AST + kA];
        unsigned a1 = As[r1 * AST + kA];
        unsigned a2 = As[r0 * AST + kB];
        unsigned a3 = As[r1 * AST + kB];
#pragma unroll
        for (int nt = 0; nt < 4; nt++) {
            int n = nt * 32 + wc * 8 + g;
            unsigned b0 = Ws[(kA << 7) | (n ^ ((kA & 3) << 3))];
            unsigned b1 = Ws[(kB << 7) | (n ^ ((kB & 3) << 3))];
            mma_tf32(acc[nt], a0, a1, a2, a3, b0, b1);
        }
    }

#pragma unroll
    for (int nt = 0; nt < 4; nt++) {
        int col = nt * 32 + wc * 8 + tig * 2;
        if (col < 64) {           // P -> fp16
            size_t o0 = (size_t)(rowBase + r0) * 64 + col;
            size_t o1 = (size_t)(rowBase + r1) * 64 + col;
            *reinterpret_cast<__half2*>(&g_Ph[o0]) = __floats2half2_rn(acc[nt][0], acc[nt][1]);
            *reinterpret_cast<__half2*>(&g_Ph[o1]) = __floats2half2_rn(acc[nt][2], acc[nt][3]);
        } else {                  // R -> fp32, bias + relu
            int c = col - 64;
            float bx = rb[c], by = rb[c + 1];
            size_t o0 = (size_t)(rowBase + r0) * 64 + c;
            size_t o1 = (size_t)(rowBase + r1) * 64 + c;
            *reinterpret_cast<float2*>(&g_R[o0]) =
                make_float2(fmaxf(acc[nt][0] + bx, 0.f), fmaxf(acc[nt][1] + by, 0.f));
            *reinterpret_cast<float2*>(&g_R[o1]) =
                make_float2(fmaxf(acc[nt][2] + bx, 0.f), fmaxf(acc[nt][3] + by, 0.f));
        }
    }
}

// ---------------- gather core: acc = sum_{e: dst=n} P[src_e] (fp16 -> fp32) ----------------
__device__ __forceinline__ float4 gather_node(int n, int lane) {
    int beg = g_off[n], end = g_off[n + 1];
    const uint2* __restrict__ P2 = reinterpret_cast<const uint2*>(g_Ph);
    float4 acc = make_float4(0.f, 0.f, 0.f, 0.f);
    int j = beg;
    for (; j + 3 < end; j += 4) {
        int s0 = __ldg(&g_esrc[j]);
        int s1 = __ldg(&g_esrc[j + 1]);
        int s2 = __ldg(&g_esrc[j + 2]);
        int s3 = __ldg(&g_esrc[j + 3]);
        uint2 u0 = __ldg(&P2[(size_t)s0 * 16 + lane]);
        uint2 u1 = __ldg(&P2[(size_t)s1 * 16 + lane]);
        uint2 u2 = __ldg(&P2[(size_t)s2 * 16 + lane]);
        uint2 u3 = __ldg(&P2[(size_t)s3 * 16 + lane]);
#pragma unroll
        for (int q = 0; q < 4; q++) {
            uint2 u = (q == 0) ? u0 : (q == 1) ? u1 : (q == 2) ? u2 : u3;
            float2 lo = __half22float2(*reinterpret_cast<const __half2*>(&u.x));
            float2 hi = __half22float2(*reinterpret_cast<const __half2*>(&u.y));
            acc.x += lo.x; acc.y += lo.y; acc.z += hi.x; acc.w += hi.y;
        }
    }
    for (; j < end; j++) {
        int s = __ldg(&g_esrc[j]);
        uint2 u = __ldg(&P2[(size_t)s * 16 + lane]);
        float2 lo = __half22float2(*reinterpret_cast<const __half2*>(&u.x));
        float2 hi = __half22float2(*reinterpret_cast<const __half2*>(&u.y));
        acc.x += lo.x; acc.y += lo.y; acc.z += hi.x; acc.w += hi.y;
    }
    return acc;
}

__device__ __forceinline__ float4 make_h(float4 acc, float4 b, float4 r) {
    float4 h;
    h.x = fmaxf(acc.x + b.x, 0.f) + r.x;
    h.y = fmaxf(acc.y + b.y, 0.f) + r.y;
    h.z = fmaxf(acc.z + b.z, 0.f) + r.z;
    h.w = fmaxf(acc.w + b.w, 0.f) + r.w;
    return h;
}

// ---------------- agg for layers 0,1: writes H = relu(acc+gb)+R ----------------
__global__ void agg_h(const float* __restrict__ gb) {
    unsigned tid = blockIdx.x * 256u + threadIdx.x;
    unsigned n = tid >> 4;
    if (n >= NN) return;
    int lane = tid & 15;
    float4 acc = gather_node(n, lane);
    float4 b = *reinterpret_cast<const float4*>(&gb[lane * 4]);
    float4 r = reinterpret_cast<const float4*>(g_R)[(size_t)n * 16 + lane];
    reinterpret_cast<float4*>(g_H)[(size_t)n * 16 + lane] = make_h(acc, b, r);
}

// ---------------- agg for layer 2 fused with sum-pool ----------------
__global__ void agg_pool(const float* __restrict__ gb, const int* __restrict__ gid) {
    unsigned tid = blockIdx.x * 256u + threadIdx.x;
    unsigned n = tid >> 4;
    if (n >= NN) return;
    int lane = tid & 15;
    float4 acc = gather_node(n, lane);
    float4 b = *reinterpret_cast<const float4*>(&gb[lane * 4]);
    float4 r = reinterpret_cast<const float4*>(g_R)[(size_t)n * 16 + lane];
    float4 h = make_h(acc, b, r);
    int g = __ldg(&gid[n]);
    red4(&g_GF[(size_t)g * 64 + lane * 4], h);
}

// ---------------- classifier MLP ----------------
// 16 graphs per block: weight traffic /16
__global__ void mlp1_kernel(const float* __restrict__ cW1, const float* __restrict__ cb1) {
    __shared__ float W[64 * 128];
    int t = threadIdx.x;
    for (int i = t; i < 64 * 128; i += 256) W[i] = cW1[i];
    __syncthreads();
    int oc = t & 127;
    int half = t >> 7;
    float bias = __ldg(&cb1[oc]);
#pragma unroll
    for (int i = 0; i < 8; i++) {
        int g = blockIdx.x * 16 + half * 8 + i;
        const float* gf = &g_GF[(size_t)g * 64];
        float s = bias;
#pragma unroll 8
        for (int k = 0; k < 64; k++) s += __ldg(&gf[k]) * W[k * 128 + oc];
        g_HID[(size_t)g * 128 + oc] = fmaxf(s, 0.f);
    }
}

__global__ void mlp2_kernel(const float* __restrict__ cW2, const float* __restrict__ cb2,
                            float* __restrict__ out) {
    __shared__ float W[128 * 2];
    int t = threadIdx.x;
    if (t < 256) W[t] = cW2[t];
    __syncthreads();
    unsigned tid = blockIdx.x * 256u + threadIdx.x;
    unsigned g = tid >> 1;
    int cls = tid & 1;
    if (g >= NG) return;
    float s = __ldg(&cb2[cls]);
    const float* hd = &g_HID[(size_t)g * 128];
#pragma unroll 8
    for (int k = 0; k < 128; k++) s += hd[k] * W[k * 2 + cls];
    out[g * 2 + cls] = s;
}

// ---------------- launch ----------------
extern "C" void kernel_launch(void* const* d_in, const int* in_sizes, int n_in,
                              void* d_out, int out_size) {
    const float* node_feats = (const float*)d_in[0];
    const int*   src        = (const int*)d_in[1];
    const int*   dst        = (const int*)d_in[2];
    const int*   gid        = (const int*)d_in[3];
    const float* gW[3] = {(const float*)d_in[4],  (const float*)d_in[8],  (const float*)d_in[12]};
    const float* gb[3] = {(const float*)d_in[5],  (const float*)d_in[9],  (const float*)d_in[13]};
    const float* rW[3] = {(const float*)d_in[6],  (const float*)d_in[10], (const float*)d_in[14]};
    const float* rb[3] = {(const float*)d_in[7],  (const float*)d_in[11], (const float*)d_in[15]};
    const float* cW1 = (const float*)d_in[16];
    const float* cb1 = (const float*)d_in[17];
    const float* cW2 = (const float*)d_in[18];
    const float* cb2 = (const float*)d_in[19];
    float* out = (float*)d_out;

    float* gfp; cudaGetSymbolAddress((void**)&gfp, g_GF);

    const int EDGE_BLOCKS = (NE + 255) / 256;   // 31250
    const int GEMM_BLOCKS = NN / 32;            // 15625
    const int AGG_BLOCKS  = (NN * 16) / 256;    // 31250
    const int ZM_BLOCKS   = (NN + 255) / 256;   // covers NN and NG*16

    cudaStream_t s2 = g_aux.s;

    // fork: CSR build + zeroing on side stream, layer-0 GEMM on main stream
    cudaEventRecord(g_aux.eFork, 0);
    cudaStreamWaitEvent(s2, g_aux.eFork, 0);

    zero_misc_kernel<<<ZM_BLOCKS, 256, 0, s2>>>(gfp);
    hist_kernel<<<EDGE_BLOCKS, 256, 0, s2>>>(dst);
    scan1_kernel<<<NB, 256, 0, s2>>>();
    scan2_kernel<<<1, 512, 0, s2>>>();
    scan3_kernel<<<NB, 256, 0, s2>>>();
    scatter_kernel<<<EDGE_BLOCKS, 256, 0, s2>>>(src, dst);

    gemm_l0<<<GEMM_BLOCKS, 256>>>(node_feats, gW[0], rW[0], rb[0]);

    // join
    cudaEventRecord(g_aux.eJoin, s2);
    cudaStreamWaitEvent(0, g_aux.eJoin, 0);

    // layer 0 agg -> H
    agg_h<<<AGG_BLOCKS, 256>>>(gb[0]);
    // layer 1
    gemm64<<<GEMM_BLOCKS, 256>>>(gW[1], rW[1], rb[1]);
    agg_h<<<AGG_BLOCKS, 256>>>(gb[1]);
    // layer 2 (agg fused with pool)
    gemm64<<<GEMM_BLOCKS, 256>>>(gW[2], rW[2], rb[2]);
    agg_pool<<<AGG_BLOCKS, 256>>>(gb[2], gid);

    // classifier
    mlp1_kernel<<<NG / 16, 256>>>(cW1, cb1);
    mlp2_kernel<<<(NG * 2) / 256, 256>>>(cW2, cb2, out);
}

// round 6
// speedup vs baseline: 3.5541x; 1.2680x over previous
#include <cuda_runtime.h>
#include <cuda_fp16.h>
#include <cstdint>

#define NN      500000
#define NE      8000000
#define NG      16384
#define INF     74
#define HID     64
#define CH      128
#define NB      489          // ceil(NN/1024) for the scan
#define NT      (NN / 32)    // 15625 row tiles
#define GRID_L0 592
#define GRID_64 740

// ---------------- scratch (device globals; no allocation) ----------------
__device__ __half g_Ph [(size_t)NN * HID];  // h @ gW, fp16 (L2-pinned)
__device__ float  g_R  [(size_t)NN * HID];  // relu(h @ rW + rb), streaming
__device__ float  g_H  [(size_t)NN * HID];  // layer output H, streaming
__device__ float  g_GF [(size_t)NG * HID];  // pooled graph features
__device__ float  g_HID[(size_t)NG * CH];   // classifier hidden

// CSR build scratch
__device__ int g_cnt [NN];
__device__ int g_off [NN + 1];
__device__ int g_cur [NN];
__device__ int g_bsum [512];
__device__ int g_esrc[NE];                  // src ids grouped by dst (L2-pinned)

// ---------------- side stream + events + smem opt-in (once; no device mem) ----------------
__global__ void __launch_bounds__(256) gemm_l0(const float*, const float*, const float*, const float*);
struct AuxRes {
    cudaStream_t s;
    cudaEvent_t eFork, eJoin;
    AuxRes() {
        cudaStreamCreate(&s);
        cudaEventCreateWithFlags(&eFork, cudaEventDisableTiming);
        cudaEventCreateWithFlags(&eJoin, cudaEventDisableTiming);
        cudaFuncSetAttribute(gemm_l0, cudaFuncAttributeMaxDynamicSharedMemorySize, 56 * 1024);
    }
};
static AuxRes g_aux;

// ---------------- helpers ----------------
__device__ __forceinline__ void red4(float* p, float4 v) {
    asm volatile("red.global.add.v4.f32 [%0], {%1,%2,%3,%4};"
                 :: "l"(p), "f"(v.x), "f"(v.y), "f"(v.z), "f"(v.w)
                 : "memory");
}

__device__ __forceinline__ unsigned long long mk_pol_last() {
    unsigned long long p;
    asm("createpolicy.fractional.L2::evict_last.b64 %0, 1.0;" : "=l"(p));
    return p;
}
__device__ __forceinline__ uint2 ld_el_u2(const uint2* a, unsigned long long pol) {
    uint2 r;
    asm("ld.global.nc.L2::cache_hint.v2.u32 {%0,%1}, [%2], %3;"
        : "=r"(r.x), "=r"(r.y) : "l"(a), "l"(pol));
    return r;
}
__device__ __forceinline__ int ld_el_s32(const int* a, unsigned long long pol) {
    int r;
    asm("ld.global.nc.L2::cache_hint.b32 %0, [%1], %2;" : "=r"(r) : "l"(a), "l"(pol));
    return r;
}
__device__ __forceinline__ void st_el_u32(unsigned* a, unsigned v, unsigned long long pol) {
    asm volatile("st.global.L2::cache_hint.b32 [%0], %1, %2;" :: "l"(a), "r"(v), "l"(pol) : "memory");
}

__device__ __forceinline__ unsigned tf32r(float x) {
    unsigned u;
    asm("cvt.rna.tf32.f32 %0, %1;" : "=r"(u) : "f"(x));
    return u;
}

__device__ __forceinline__ void mma_tf32(float* d,
        unsigned a0, unsigned a1, unsigned a2, unsigned a3,
        unsigned b0, unsigned b1) {
    asm volatile(
        "mma.sync.aligned.m16n8k8.row.col.f32.tf32.tf32.f32 "
        "{%0,%1,%2,%3}, {%4,%5,%6,%7}, {%8,%9}, {%0,%1,%2,%3};"
        : "+f"(d[0]), "+f"(d[1]), "+f"(d[2]), "+f"(d[3])
        : "r"(a0), "r"(a1), "r"(a2), "r"(a3), "r"(b0), "r"(b1));
}

__global__ void zero_misc_kernel(float* __restrict__ gf) {
    unsigned i = blockIdx.x * 256u + threadIdx.x;
    if (i < NN) g_cnt[i] = 0;
    if (i < NG * 16u) reinterpret_cast<float4*>(gf)[i] = make_float4(0.f, 0.f, 0.f, 0.f);
}

// ---------------- CSR build: hist -> scan -> scatter ----------------
__global__ void hist_kernel(const int* __restrict__ dst) {
    unsigned e = blockIdx.x * 256u + threadIdx.x;
    if (e < NE) atomicAdd(&g_cnt[__ldcs(&dst[e])], 1);
}

__global__ void scan1_kernel() {
    __shared__ int sm[256];
    int b = blockIdx.x, t = threadIdx.x;
    int base = b * 1024 + t * 4;
    int v[4];
#pragma unroll
    for (int i = 0; i < 4; i++) {
        int idx = base + i;
        v[i] = (idx < NN) ? g_cnt[idx] : 0;
    }
    int s = v[0] + v[1] + v[2] + v[3];
    sm[t] = s;
    __syncthreads();
    for (int d = 1; d < 256; d <<= 1) {
        int x = (t >= d) ? sm[t - d] : 0;
        __syncthreads();
        sm[t] += x;
        __syncthreads();
    }
    int excl = sm[t] - s;
    if (t == 255) g_bsum[b] = sm[255];
    int run = excl;
#pragma unroll
    for (int i = 0; i < 4; i++) {
        int idx = base + i;
        if (idx < NN) g_off[idx] = run;
        run += v[i];
    }
}

// merged scan2+scan3: each block sums g_bsum[0..b) itself (489 ints, trivial)
__global__ void scan23_kernel() {
    __shared__ int sm[256];
    int b = blockIdx.x, t = threadIdx.x;
    int s = 0;
    for (int i = t; i < b; i += 256) s += g_bsum[i];
    sm[t] = s;
    __syncthreads();
    for (int d = 128; d > 0; d >>= 1) {
        if (t < d) sm[t] += sm[t + d];
        __syncthreads();
    }
    int add = sm[0];
    int base = b * 1024 + t * 4;
#pragma unroll
    for (int i = 0; i < 4; i++) {
        int idx = base + i;
        if (idx < NN) {
            int o = g_off[idx] + add;
            g_off[idx] = o;
            g_cur[idx] = o;
        }
    }
    if (b == NB - 1 && t == 0) g_off[NN] = add + g_bsum[NB - 1];
}

__global__ void scatter_kernel(const int* __restrict__ src, const int* __restrict__ dst) {
    unsigned e = blockIdx.x * 256u + threadIdx.x;
    if (e >= NE) return;
    unsigned long long pol = mk_pol_last();
    int d = __ldcs(&dst[e]);
    int pos = atomicAdd(&g_cur[d], 1);
    st_el_u32(reinterpret_cast<unsigned*>(&g_esrc[pos]), (unsigned)__ldcs(&src[e]), pol);
}

// ---------------- layer-0 GEMM (K padded 74->80), persistent, both W resident ----------------
__global__ void __launch_bounds__(256) gemm_l0(
        const float* __restrict__ hin,
        const float* __restrict__ gW,
        const float* __restrict__ rW,
        const float* __restrict__ rb) {
    constexpr int KP = 80, AST = 84;
    extern __shared__ unsigned dsm[];
    unsigned* Ws0 = dsm;                 // 80*64
    unsigned* Ws1 = dsm + KP * 64;       // 80*64
    unsigned* As  = dsm + 2 * KP * 64;   // 32*84

    const int t = threadIdx.x;
    const int lane = t & 31;
    const int wid = t >> 5;
    const int g = lane >> 2;
    const int tig = lane & 3;
    const int wr = wid >> 2;
    const int wc = wid & 3;
    const int r0l = wr * 16 + g;
    const int r1l = r0l + 8;
    unsigned long long pol = mk_pol_last();

    // load both weight tiles once (swizzled)
    for (int i = t; i < KP * 64; i += 256) {
        int k = i >> 6, c = i & 63;
        int sw = (k << 6) | (c ^ ((k & 3) << 3));
        Ws0[sw] = tf32r((k < INF) ? gW[k * 64 + c] : 0.f);
        Ws1[sw] = tf32r((k < INF) ? rW[k * 64 + c] : 0.f);
    }
    __syncthreads();

    for (int tile = blockIdx.x; tile < NT; tile += GRID_L0) {
        const int rowBase = tile * 32;
        for (int i = t; i < 32 * KP; i += 256) {
            int r = i / KP, k = i - r * KP;
            float v = (k < INF) ? __ldcs(&hin[(size_t)(rowBase + r) * INF + k]) : 0.f;
            As[r * AST + k] = tf32r(v);
        }
        __syncthreads();

        float accP[2][4] = {{0.f,0.f,0.f,0.f},{0.f,0.f,0.f,0.f}};
        float accR[2][4] = {{0.f,0.f,0.f,0.f},{0.f,0.f,0.f,0.f}};
#pragma unroll
        for (int ks = 0; ks < KP / 8; ks++) {
            const int kA = ks * 8 + tig, kB = kA + 4;
            unsigned a0 = As[r0l * AST + kA];
            unsigned a1 = As[r1l * AST + kA];
            unsigned a2 = As[r0l * AST + kB];
            unsigned a3 = As[r1l * AST + kB];
#pragma unroll
            for (int nt = 0; nt < 2; nt++) {
                int n = wc * 16 + nt * 8 + g;
                int swA = (kA << 6) | (n ^ ((kA & 3) << 3));
                int swB = (kB << 6) | (n ^ ((kB & 3) << 3));
                mma_tf32(accP[nt], a0, a1, a2, a3, Ws0[swA], Ws0[swB]);
                mma_tf32(accR[nt], a0, a1, a2, a3, Ws1[swA], Ws1[swB]);
            }
        }
#pragma unroll
        for (int nt = 0; nt < 2; nt++) {
            int col = wc * 16 + nt * 8 + tig * 2;
            size_t o0 = (size_t)(rowBase + r0l) * 64 + col;
            size_t o1 = (size_t)(rowBase + r1l) * 64 + col;
            __half2 p0 = __floats2half2_rn(accP[nt][0], accP[nt][1]);
            __half2 p1 = __floats2half2_rn(accP[nt][2], accP[nt][3]);
            st_el_u32(reinterpret_cast<unsigned*>(&g_Ph[o0]), *reinterpret_cast<unsigned*>(&p0), pol);
            st_el_u32(reinterpret_cast<unsigned*>(&g_Ph[o1]), *reinterpret_cast<unsigned*>(&p1), pol);
            float bx = rb[col], by = rb[col + 1];
            __stcs(reinterpret_cast<float2*>(&g_R[o0]),
                   make_float2(fmaxf(accR[nt][0] + bx, 0.f), fmaxf(accR[nt][1] + by, 0.f)));
            __stcs(reinterpret_cast<float2*>(&g_R[o1]),
                   make_float2(fmaxf(accR[nt][2] + bx, 0.f), fmaxf(accR[nt][3] + by, 0.f)));
        }
        __syncthreads();
    }
}

// ---------------- layers 1/2 GEMM: persistent, single pass, 128 output cols ----------------
__global__ void __launch_bounds__(256) gemm64(
        const float* __restrict__ gW,
        const float* __restrict__ rW,
        const float* __restrict__ rb) {
    constexpr int AST = 68;
    __shared__ unsigned As[32 * AST];
    __shared__ unsigned Ws[64 * 128];

    const int t = threadIdx.x;
    const int lane = t & 31;
    const int wid = t >> 5;
    const int g = lane >> 2;
    const int tig = lane & 3;
    const int wr = wid >> 2;
    const int wc = wid & 3;
    const int r0l = wr * 16 + g;
    const int r1l = r0l + 8;
    unsigned long long pol = mk_pol_last();

    for (int i = t; i < 64 * 128; i += 256) {
        int k = i >> 7, c = i & 127;
        float v = (c < 64) ? gW[k * 64 + c] : rW[k * 64 + (c - 64)];
        Ws[(k << 7) | (c ^ ((k & 3) << 3))] = tf32r(v);
    }
    __syncthreads();

    for (int tile = blockIdx.x; tile < NT; tile += GRID_64) {
        const int rowBase = tile * 32;
        for (int i = t; i < 32 * 16; i += 256) {
            int r = i >> 4, k4 = i & 15;
            float4 v = __ldcs(reinterpret_cast<const float4*>(
                                  &g_H[(size_t)(rowBase + r) * 64 + k4 * 4]));
            uint4 o;
            o.x = tf32r(v.x); o.y = tf32r(v.y); o.z = tf32r(v.z); o.w = tf32r(v.w);
            *reinterpret_cast<uint4*>(&As[r * AST + k4 * 4]) = o;
        }
        __syncthreads();

        float acc[4][4];
#pragma unroll
        for (int i = 0; i < 4; i++)
#pragma unroll
            for (int j = 0; j < 4; j++) acc[i][j] = 0.f;

#pragma unroll
        for (int ks = 0; ks < 8; ks++) {
            const int kA = ks * 8 + tig, kB = kA + 4;
            unsigned a0 = As[r0l * AST + kA];
            unsigned a1 = As[r1l * AST + kA];
            unsigned a2 = As[r0l * AST + kB];
            unsigned a3 = As[r1l * AST + kB];
#pragma unroll
            for (int nt = 0; nt < 4; nt++) {
                int n = nt * 32 + wc * 8 + g;
                unsigned b0 = Ws[(kA << 7) | (n ^ ((kA & 3) << 3))];
                unsigned b1 = Ws[(kB << 7) | (n ^ ((kB & 3) << 3))];
                mma_tf32(acc[nt], a0, a1, a2, a3, b0, b1);
            }
        }

#pragma unroll
        for (int nt = 0; nt < 4; nt++) {
            int col = nt * 32 + wc * 8 + tig * 2;
            if (col < 64) {
                size_t o0 = (size_t)(rowBase + r0l) * 64 + col;
                size_t o1 = (size_t)(rowBase + r1l) * 64 + col;
                __half2 p0 = __floats2half2_rn(acc[nt][0], acc[nt][1]);
                __half2 p1 = __floats2half2_rn(acc[nt][2], acc[nt][3]);
                st_el_u32(reinterpret_cast<unsigned*>(&g_Ph[o0]), *reinterpret_cast<unsigned*>(&p0), pol);
                st_el_u32(reinterpret_cast<unsigned*>(&g_Ph[o1]), *reinterpret_cast<unsigned*>(&p1), pol);
            } else {
                int c = col - 64;
                float bx = rb[c], by = rb[c + 1];
                size_t o0 = (size_t)(rowBase + r0l) * 64 + c;
                size_t o1 = (size_t)(rowBase + r1l) * 64 + c;
                __stcs(reinterpret_cast<float2*>(&g_R[o0]),
                       make_float2(fmaxf(acc[nt][0] + bx, 0.f), fmaxf(acc[nt][1] + by, 0.f)));
                __stcs(reinterpret_cast<float2*>(&g_R[o1]),
                       make_float2(fmaxf(acc[nt][2] + bx, 0.f), fmaxf(acc[nt][3] + by, 0.f)));
            }
        }
        __syncthreads();
    }
}

// ---------------- gather core: acc = sum_{e: dst=n} P[src_e] (fp16 -> fp32, L2-pinned) ----------------
__device__ __forceinline__ float4 gather_node(int n, int lane, unsigned long long pol) {
    int beg = g_off[n], end = g_off[n + 1];
    const uint2* __restrict__ P2 = reinterpret_cast<const uint2*>(g_Ph);
    float4 acc = make_float4(0.f, 0.f, 0.f, 0.f);
    int j = beg;
    for (; j + 3 < end; j += 4) {
        int s0 = ld_el_s32(&g_esrc[j], pol);
        int s1 = ld_el_s32(&g_esrc[j + 1], pol);
        int s2 = ld_el_s32(&g_esrc[j + 2], pol);
        int s3 = ld_el_s32(&g_esrc[j + 3], pol);
        uint2 u0 = ld_el_u2(&P2[(size_t)s0 * 16 + lane], pol);
        uint2 u1 = ld_el_u2(&P2[(size_t)s1 * 16 + lane], pol);
        uint2 u2 = ld_el_u2(&P2[(size_t)s2 * 16 + lane], pol);
        uint2 u3 = ld_el_u2(&P2[(size_t)s3 * 16 + lane], pol);
#pragma unroll
        for (int q = 0; q < 4; q++) {
            uint2 u = (q == 0) ? u0 : (q == 1) ? u1 : (q == 2) ? u2 : u3;
            float2 lo = __half22float2(*reinterpret_cast<const __half2*>(&u.x));
            float2 hi = __half22float2(*reinterpret_cast<const __half2*>(&u.y));
            acc.x += lo.x; acc.y += lo.y; acc.z += hi.x; acc.w += hi.y;
        }
    }
    for (; j < end; j++) {
        int s = ld_el_s32(&g_esrc[j], pol);
        uint2 u = ld_el_u2(&P2[(size_t)s * 16 + lane], pol);
        float2 lo = __half22float2(*reinterpret_cast<const __half2*>(&u.x));
        float2 hi = __half22float2(*reinterpret_cast<const __half2*>(&u.y));
        acc.x += lo.x; acc.y += lo.y; acc.z += hi.x; acc.w += hi.y;
    }
    return acc;
}

__device__ __forceinline__ float4 make_h(float4 acc, float4 b, float4 r) {
    float4 h;
    h.x = fmaxf(acc.x + b.x, 0.f) + r.x;
    h.y = fmaxf(acc.y + b.y, 0.f) + r.y;
    h.z = fmaxf(acc.z + b.z, 0.f) + r.z;
    h.w = fmaxf(acc.w + b.w, 0.f) + r.w;
    return h;
}

// ---------------- agg for layers 0,1: writes H = relu(acc+gb)+R ----------------
__global__ void agg_h(const float* __restrict__ gb) {
    unsigned tid = blockIdx.x * 256u + threadIdx.x;
    unsigned n = tid >> 4;
    if (n >= NN) return;
    int lane = tid & 15;
    unsigned long long pol = mk_pol_last();
    float4 acc = gather_node(n, lane, pol);
    float4 b = *reinterpret_cast<const float4*>(&gb[lane * 4]);
    float4 r = __ldcs(&reinterpret_cast<const float4*>(g_R)[(size_t)n * 16 + lane]);
    __stcs(&reinterpret_cast<float4*>(g_H)[(size_t)n * 16 + lane], make_h(acc, b, r));
}

// ---------------- agg for layer 2 fused with sum-pool ----------------
__global__ void agg_pool(const float* __restrict__ gb, const int* __restrict__ gid) {
    unsigned tid = blockIdx.x * 256u + threadIdx.x;
    unsigned n = tid >> 4;
    if (n >= NN) return;
    int lane = tid & 15;
    unsigned long long pol = mk_pol_last();
    float4 acc = gather_node(n, lane, pol);
    float4 b = *reinterpret_cast<const float4*>(&gb[lane * 4]);
    float4 r = __ldcs(&reinterpret_cast<const float4*>(g_R)[(size_t)n * 16 + lane]);
    float4 h = make_h(acc, b, r);
    int g = __ldg(&gid[n]);
    red4(&g_GF[(size_t)g * 64 + lane * 4], h);
}

// ---------------- classifier MLP ----------------
__global__ void mlp1_kernel(const float* __restrict__ cW1, const float* __restrict__ cb1) {
    __shared__ float W[64 * 128];
    int t = threadIdx.x;
    for (int i = t; i < 64 * 128; i += 256) W[i] = cW1[i];
    __syncthreads();
    int oc = t & 127;
    int half = t >> 7;
    float bias = __ldg(&cb1[oc]);
#pragma unroll
    for (int i = 0; i < 8; i++) {
        int g = blockIdx.x * 16 + half * 8 + i;
        const float* gf = &g_GF[(size_t)g * 64];
        float s = bias;
#pragma unroll 8
        for (int k = 0; k < 64; k++) s += __ldg(&gf[k]) * W[k * 128 + oc];
        g_HID[(size_t)g * 128 + oc] = fmaxf(s, 0.f);
    }
}

__global__ void mlp2_kernel(const float* __restrict__ cW2, const float* __restrict__ cb2,
                            float* __restrict__ out) {
    __shared__ float W[128 * 2];
    int t = threadIdx.x;
    if (t < 256) W[t] = cW2[t];
    __syncthreads();
    unsigned tid = blockIdx.x * 256u + threadIdx.x;
    unsigned g = tid >> 1;
    int cls = tid & 1;
    if (g >= NG) return;
    float s = __ldg(&cb2[cls]);
    const float* hd = &g_HID[(size_t)g * 128];
#pragma unroll 8
    for (int k = 0; k < 128; k++) s += hd[k] * W[k * 2 + cls];
    out[g * 2 + cls] = s;
}

// ---------------- launch ----------------
extern "C" void kernel_launch(void* const* d_in, const int* in_sizes, int n_in,
                              void* d_out, int out_size) {
    const float* node_feats = (const float*)d_in[0];
    const int*   src        = (const int*)d_in[1];
    const int*   dst        = (const int*)d_in[2];
    const int*   gid        = (const int*)d_in[3];
    const float* gW[3] = {(const float*)d_in[4],  (const float*)d_in[8],  (const float*)d_in[12]};
    const float* gb[3] = {(const float*)d_in[5],  (const float*)d_in[9],  (const float*)d_in[13]};
    const float* rW[3] = {(const float*)d_in[6],  (const float*)d_in[10], (const float*)d_in[14]};
    const float* rb[3] = {(const float*)d_in[7],  (const float*)d_in[11], (const float*)d_in[15]};
    const float* cW1 = (const float*)d_in[16];
    const float* cb1 = (const float*)d_in[17];
    const float* cW2 = (const float*)d_in[18];
    const float* cb2 = (const float*)d_in[19];
    float* out = (float*)d_out;

    float* gfp; cudaGetSymbolAddress((void**)&gfp, g_GF);

    const int EDGE_BLOCKS = (NE + 255) / 256;   // 31250
    const int AGG_BLOCKS  = (NN * 16) / 256;    // 31250
    const int ZM_BLOCKS   = (NN + 255) / 256;
    const int DSM_L0      = (2 * 80 * 64 + 32 * 84) * 4;   // 51712 B

    cudaStream_t s2 = g_aux.s;

    // fork: CSR build + zeroing on side stream, layer-0 GEMM on main stream
    cudaEventRecord(g_aux.eFork, 0);
    cudaStreamWaitEvent(s2, g_aux.eFork, 0);

    zero_misc_kernel<<<ZM_BLOCKS, 256, 0, s2>>>(gfp);
    hist_kernel<<<EDGE_BLOCKS, 256, 0, s2>>>(dst);
    scan1_kernel<<<NB, 256, 0, s2>>>();
    scan23_kernel<<<NB, 256, 0, s2>>>();
    scatter_kernel<<<EDGE_BLOCKS, 256, 0, s2>>>(src, dst);

    gemm_l0<<<GRID_L0, 256, DSM_L0>>>(node_feats, gW[0], rW[0], rb[0]);

    // join
    cudaEventRecord(g_aux.eJoin, s2);
    cudaStreamWaitEvent(0, g_aux.eJoin, 0);

    // layer 0 agg -> H
    agg_h<<<AGG_BLOCKS, 256>>>(gb[0]);
    // layer 1
    gemm64<<<GRID_64, 256>>>(gW[1], rW[1], rb[1]);
    agg_h<<<AGG_BLOCKS, 256>>>(gb[1]);
    // layer 2 (agg fused with pool)
    gemm64<<<GRID_64, 256>>>(gW[2], rW[2], rb[2]);
    agg_pool<<<AGG_BLOCKS, 256>>>(gb[2], gid);

    // classifier
    mlp1_kernel<<<NG / 16, 256>>>(cW1, cb1);
    mlp2_kernel<<<(NG * 2) / 256, 256>>>(cW2, cb2, out);
}

// round 7
// speedup vs baseline: 3.6778x; 1.0348x over previous
#include <cuda_runtime.h>
#include <cuda_fp16.h>
#include <cstdint>

#define NN      500000
#define NE      8000000
#define NG      16384
#define INF     74
#define HID     64
#define CH      128
#define NB      489          // ceil(NN/1024) for the scan
#define NT      (NN / 32)    // 15625 row tiles
#define GRID_L0 592
#define GRID_64 740

// ---------------- scratch (device globals; no allocation) ----------------
__device__ __half g_Ph [(size_t)NN * HID];  // h @ gW, fp16 (L2-pinned)
__device__ float  g_R  [(size_t)NN * HID];  // relu(h @ rW + rb), streaming
__device__ float  g_H  [(size_t)NN * HID];  // layer output H, streaming
__device__ float  g_GF [(size_t)NG * HID];  // pooled graph features

// CSR build scratch
__device__ int g_cnt [NN];
__device__ int g_off [NN + 1];
__device__ int g_cur [NN];
__device__ int g_bsum [512];
__device__ int g_esrc[NE];                  // src ids grouped by dst (L2-pinned)

// ---------------- side stream + events + smem opt-in (once; no device mem) ----------------
__global__ void __launch_bounds__(256) gemm_l0(const float*, const float*, const float*, const float*);
struct AuxRes {
    cudaStream_t s;
    cudaEvent_t eFork, eJoin;
    AuxRes() {
        cudaStreamCreate(&s);
        cudaEventCreateWithFlags(&eFork, cudaEventDisableTiming);
        cudaEventCreateWithFlags(&eJoin, cudaEventDisableTiming);
        cudaFuncSetAttribute(gemm_l0, cudaFuncAttributeMaxDynamicSharedMemorySize, 56 * 1024);
    }
};
static AuxRes g_aux;

// ---------------- helpers ----------------
__device__ __forceinline__ void red4(float* p, float4 v) {
    asm volatile("red.global.add.v4.f32 [%0], {%1,%2,%3,%4};"
                 :: "l"(p), "f"(v.x), "f"(v.y), "f"(v.z), "f"(v.w)
                 : "memory");
}

__device__ __forceinline__ unsigned long long mk_pol_last() {
    unsigned long long p;
    asm("createpolicy.fractional.L2::evict_last.b64 %0, 1.0;" : "=l"(p));
    return p;
}
__device__ __forceinline__ uint2 ld_el_u2(const uint2* a, unsigned long long pol) {
    uint2 r;
    asm("ld.global.nc.L2::cache_hint.v2.u32 {%0,%1}, [%2], %3;"
        : "=r"(r.x), "=r"(r.y) : "l"(a), "l"(pol));
    return r;
}
__device__ __forceinline__ int ld_el_s32(const int* a, unsigned long long pol) {
    int r;
    asm("ld.global.nc.L2::cache_hint.b32 %0, [%1], %2;" : "=r"(r) : "l"(a), "l"(pol));
    return r;
}
__device__ __forceinline__ void st_el_u32(unsigned* a, unsigned v, unsigned long long pol) {
    asm volatile("st.global.L2::cache_hint.b32 [%0], %1, %2;" :: "l"(a), "r"(v), "l"(pol) : "memory");
}

__device__ __forceinline__ unsigned tf32r(float x) {
    unsigned u;
    asm("cvt.rna.tf32.f32 %0, %1;" : "=r"(u) : "f"(x));
    return u;
}

__device__ __forceinline__ void mma_tf32(float* d,
        unsigned a0, unsigned a1, unsigned a2, unsigned a3,
        unsigned b0, unsigned b1) {
    asm volatile(
        "mma.sync.aligned.m16n8k8.row.col.f32.tf32.tf32.f32 "
        "{%0,%1,%2,%3}, {%4,%5,%6,%7}, {%8,%9}, {%0,%1,%2,%3};"
        : "+f"(d[0]), "+f"(d[1]), "+f"(d[2]), "+f"(d[3])
        : "r"(a0), "r"(a1), "r"(a2), "r"(a3), "r"(b0), "r"(b1));
}

__global__ void zero_misc_kernel(float* __restrict__ gf) {
    unsigned i = blockIdx.x * 256u + threadIdx.x;
    if (i < NN) g_cnt[i] = 0;
    if (i < NG * 16u) reinterpret_cast<float4*>(gf)[i] = make_float4(0.f, 0.f, 0.f, 0.f);
}

// ---------------- CSR build: hist -> scan -> scatter (int4-vectorized) ----------------
__global__ void hist_kernel(const int4* __restrict__ dst4) {
    unsigned i = blockIdx.x * 256u + threadIdx.x;
    if (i >= NE / 4) return;
    int4 d = __ldcs(&dst4[i]);
    atomicAdd(&g_cnt[d.x], 1);
    atomicAdd(&g_cnt[d.y], 1);
    atomicAdd(&g_cnt[d.z], 1);
    atomicAdd(&g_cnt[d.w], 1);
}

__global__ void scan1_kernel() {
    __shared__ int sm[256];
    int b = blockIdx.x, t = threadIdx.x;
    int base = b * 1024 + t * 4;
    int v[4];
#pragma unroll
    for (int i = 0; i < 4; i++) {
        int idx = base + i;
        v[i] = (idx < NN) ? g_cnt[idx] : 0;
    }
    int s = v[0] + v[1] + v[2] + v[3];
    sm[t] = s;
    __syncthreads();
    for (int d = 1; d < 256; d <<= 1) {
        int x = (t >= d) ? sm[t - d] : 0;
        __syncthreads();
        sm[t] += x;
        __syncthreads();
    }
    int excl = sm[t] - s;
    if (t == 255) g_bsum[b] = sm[255];
    int run = excl;
#pragma unroll
    for (int i = 0; i < 4; i++) {
        int idx = base + i;
        if (idx < NN) g_off[idx] = run;
        run += v[i];
    }
}

// merged scan2+scan3: each block sums g_bsum[0..b) itself (489 ints, trivial)
__global__ void scan23_kernel() {
    __shared__ int sm[256];
    int b = blockIdx.x, t = threadIdx.x;
    int s = 0;
    for (int i = t; i < b; i += 256) s += g_bsum[i];
    sm[t] = s;
    __syncthreads();
    for (int d = 128; d > 0; d >>= 1) {
        if (t < d) sm[t] += sm[t + d];
        __syncthreads();
    }
    int add = sm[0];
    int base = b * 1024 + t * 4;
#pragma unroll
    for (int i = 0; i < 4; i++) {
        int idx = base + i;
        if (idx < NN) {
            int o = g_off[idx] + add;
            g_off[idx] = o;
            g_cur[idx] = o;
        }
    }
    if (b == NB - 1 && t == 0) g_off[NN] = add + g_bsum[NB - 1];
}

__global__ void scatter_kernel(const int4* __restrict__ src4, const int4* __restrict__ dst4) {
    unsigned i = blockIdx.x * 256u + threadIdx.x;
    if (i >= NE / 4) return;
    unsigned long long pol = mk_pol_last();
    int4 s = __ldcs(&src4[i]);
    int4 d = __ldcs(&dst4[i]);
    int p0 = atomicAdd(&g_cur[d.x], 1);
    st_el_u32(reinterpret_cast<unsigned*>(&g_esrc[p0]), (unsigned)s.x, pol);
    int p1 = atomicAdd(&g_cur[d.y], 1);
    st_el_u32(reinterpret_cast<unsigned*>(&g_esrc[p1]), (unsigned)s.y, pol);
    int p2 = atomicAdd(&g_cur[d.z], 1);
    st_el_u32(reinterpret_cast<unsigned*>(&g_esrc[p2]), (unsigned)s.z, pol);
    int p3 = atomicAdd(&g_cur[d.w], 1);
    st_el_u32(reinterpret_cast<unsigned*>(&g_esrc[p3]), (unsigned)s.w, pol);
}

// ---------------- layer-0 GEMM (K padded 74->80), persistent, both W resident ----------------
__global__ void __launch_bounds__(256) gemm_l0(
        const float* __restrict__ hin,
        const float* __restrict__ gW,
        const float* __restrict__ rW,
        const float* __restrict__ rb) {
    constexpr int KP = 80, AST = 84;
    extern __shared__ unsigned dsm[];
    unsigned* Ws0 = dsm;                 // 80*64
    unsigned* Ws1 = dsm + KP * 64;       // 80*64
    unsigned* As  = dsm + 2 * KP * 64;   // 32*84

    const int t = threadIdx.x;
    const int lane = t & 31;
    const int wid = t >> 5;
    const int g = lane >> 2;
    const int tig = lane & 3;
    const int wr = wid >> 2;
    const int wc = wid & 3;
    const int r0l = wr * 16 + g;
    const int r1l = r0l + 8;
    unsigned long long pol = mk_pol_last();

    for (int i = t; i < KP * 64; i += 256) {
        int k = i >> 6, c = i & 63;
        int sw = (k << 6) | (c ^ ((k & 3) << 3));
        Ws0[sw] = tf32r((k < INF) ? gW[k * 64 + c] : 0.f);
        Ws1[sw] = tf32r((k < INF) ? rW[k * 64 + c] : 0.f);
    }
    __syncthreads();

    for (int tile = blockIdx.x; tile < NT; tile += GRID_L0) {
        const int rowBase = tile * 32;
        for (int i = t; i < 32 * KP; i += 256) {
            int r = i / KP, k = i - r * KP;
            float v = (k < INF) ? __ldcs(&hin[(size_t)(rowBase + r) * INF + k]) : 0.f;
            As[r * AST + k] = tf32r(v);
        }
        __syncthreads();

        float accP[2][4] = {{0.f,0.f,0.f,0.f},{0.f,0.f,0.f,0.f}};
        float accR[2][4] = {{0.f,0.f,0.f,0.f},{0.f,0.f,0.f,0.f}};
#pragma unroll
        for (int ks = 0; ks < KP / 8; ks++) {
            const int kA = ks * 8 + tig, kB = kA + 4;
            unsigned a0 = As[r0l * AST + kA];
            unsigned a1 = As[r1l * AST + kA];
            unsigned a2 = As[r0l * AST + kB];
            unsigned a3 = As[r1l * AST + kB];
#pragma unroll
            for (int nt = 0; nt < 2; nt++) {
                int n = wc * 16 + nt * 8 + g;
                int swA = (kA << 6) | (n ^ ((kA & 3) << 3));
                int swB = (kB << 6) | (n ^ ((kB & 3) << 3));
                mma_tf32(accP[nt], a0, a1, a2, a3, Ws0[swA], Ws0[swB]);
                mma_tf32(accR[nt], a0, a1, a2, a3, Ws1[swA], Ws1[swB]);
            }
        }
#pragma unroll
        for (int nt = 0; nt < 2; nt++) {
            int col = wc * 16 + nt * 8 + tig * 2;
            size_t o0 = (size_t)(rowBase + r0l) * 64 + col;
            size_t o1 = (size_t)(rowBase + r1l) * 64 + col;
            __half2 p0 = __floats2half2_rn(accP[nt][0], accP[nt][1]);
            __half2 p1 = __floats2half2_rn(accP[nt][2], accP[nt][3]);
            st_el_u32(reinterpret_cast<unsigned*>(&g_Ph[o0]), *reinterpret_cast<unsigned*>(&p0), pol);
            st_el_u32(reinterpret_cast<unsigned*>(&g_Ph[o1]), *reinterpret_cast<unsigned*>(&p1), pol);
            float bx = rb[col], by = rb[col + 1];
            __stcs(reinterpret_cast<float2*>(&g_R[o0]),
                   make_float2(fmaxf(accR[nt][0] + bx, 0.f), fmaxf(accR[nt][1] + by, 0.f)));
            __stcs(reinterpret_cast<float2*>(&g_R[o1]),
                   make_float2(fmaxf(accR[nt][2] + bx, 0.f), fmaxf(accR[nt][3] + by, 0.f)));
        }
        __syncthreads();
    }
}

// ---------------- layers 1/2 GEMM: persistent, prefetch-double-buffered ----------------
__global__ void __launch_bounds__(256) gemm64(
        const float* __restrict__ gW,
        const float* __restrict__ rW,
        const float* __restrict__ rb) {
    constexpr int AST = 68;
    __shared__ unsigned As[32 * AST];
    __shared__ unsigned Ws[64 * 128];

    const int t = threadIdx.x;
    const int lane = t & 31;
    const int wid = t >> 5;
    const int g = lane >> 2;
    const int tig = lane & 3;
    const int wr = wid >> 2;
    const int wc = wid & 3;
    const int r0l = wr * 16 + g;
    const int r1l = r0l + 8;
    unsigned long long pol = mk_pol_last();

    for (int i = t; i < 64 * 128; i += 256) {
        int k = i >> 7, c = i & 127;
        float v = (c < 64) ? gW[k * 64 + c] : rW[k * 64 + (c - 64)];
        Ws[(k << 7) | (c ^ ((k & 3) << 3))] = tf32r(v);
    }

    // per-thread A-slice coords: j in {t, t+256} of 512 float4s
    const int jr0 = t >> 4,          jk0 = t & 15;          // j = t
    const int jr1 = (t + 256) >> 4,  jk1 = t & 15;          // j = t+256

    int tile = blockIdx.x;
    float4 v0, v1;
    if (tile < NT) {
        v0 = __ldcs(reinterpret_cast<const float4*>(&g_H[(size_t)(tile * 32 + jr0) * 64 + jk0 * 4]));
        v1 = __ldcs(reinterpret_cast<const float4*>(&g_H[(size_t)(tile * 32 + jr1) * 64 + jk1 * 4]));
    }
    __syncthreads();

    while (tile < NT) {
        const int rowBase = tile * 32;
        // store prefetched A into smem (tf32)
        {
            uint4 o;
            o.x = tf32r(v0.x); o.y = tf32r(v0.y); o.z = tf32r(v0.z); o.w = tf32r(v0.w);
            *reinterpret_cast<uint4*>(&As[jr0 * AST + jk0 * 4]) = o;
            o.x = tf32r(v1.x); o.y = tf32r(v1.y); o.z = tf32r(v1.z); o.w = tf32r(v1.w);
            *reinterpret_cast<uint4*>(&As[jr1 * AST + jk1 * 4]) = o;
        }
        __syncthreads();

        // prefetch next tile while mma runs
        const int next = tile + GRID_64;
        if (next < NT) {
            v0 = __ldcs(reinterpret_cast<const float4*>(&g_H[(size_t)(next * 32 + jr0) * 64 + jk0 * 4]));
            v1 = __ldcs(reinterpret_cast<const float4*>(&g_H[(size_t)(next * 32 + jr1) * 64 + jk1 * 4]));
        }

        float acc[4][4];
#pragma unroll
        for (int i = 0; i < 4; i++)
#pragma unroll
            for (int j = 0; j < 4; j++) acc[i][j] = 0.f;

#pragma unroll
        for (int ks = 0; ks < 8; ks++) {
            const int kA = ks * 8 + tig, kB = kA + 4;
            unsigned a0 = As[r0l * AST + kA];
            unsigned a1 = As[r1l * AST + kA];
            unsigned a2 = As[r0l * AST + kB];
            unsigned a3 = As[r1l * AST + kB];
#pragma unroll
            for (int nt = 0; nt < 4; nt++) {
                int n = nt * 32 + wc * 8 + g;
                unsigned b0 = Ws[(kA << 7) | (n ^ ((kA & 3) << 3))];
                unsigned b1 = Ws[(kB << 7) | (n ^ ((kB & 3) << 3))];
                mma_tf32(acc[nt], a0, a1, a2, a3, b0, b1);
            }
        }

#pragma unroll
        for (int nt = 0; nt < 4; nt++) {
            int col = nt * 32 + wc * 8 + tig * 2;
            if (col < 64) {
                size_t o0 = (size_t)(rowBase + r0l) * 64 + col;
                size_t o1 = (size_t)(rowBase + r1l) * 64 + col;
                __half2 p0 = __floats2half2_rn(acc[nt][0], acc[nt][1]);
                __half2 p1 = __floats2half2_rn(acc[nt][2], acc[nt][3]);
                st_el_u32(reinterpret_cast<unsigned*>(&g_Ph[o0]), *reinterpret_cast<unsigned*>(&p0), pol);
                st_el_u32(reinterpret_cast<unsigned*>(&g_Ph[o1]), *reinterpret_cast<unsigned*>(&p1), pol);
            } else {
                int c = col - 64;
                float bx = rb[c], by = rb[c + 1];
                size_t o0 = (size_t)(rowBase + r0l) * 64 + c;
                size_t o1 = (size_t)(rowBase + r1l) * 64 + c;
                __stcs(reinterpret_cast<float2*>(&g_R[o0]),
                       make_float2(fmaxf(acc[nt][0] + bx, 0.f), fmaxf(acc[nt][1] + by, 0.f)));
                __stcs(reinterpret_cast<float2*>(&g_R[o1]),
                       make_float2(fmaxf(acc[nt][2] + bx, 0.f), fmaxf(acc[nt][3] + by, 0.f)));
            }
        }
        __syncthreads();
        tile = next;
    }
}

// ---------------- gather core: acc = sum_{e: dst=n} P[src_e] (fp16 -> fp32, L2-pinned) ----------------
__device__ __forceinline__ float4 gather_node(int n, int lane, unsigned long long pol) {
    int beg = g_off[n], end = g_off[n + 1];
    const uint2* __restrict__ P2 = reinterpret_cast<const uint2*>(g_Ph);
    float4 acc = make_float4(0.f, 0.f, 0.f, 0.f);
    int j = beg;
    for (; j + 3 < end; j += 4) {
        int s0 = ld_el_s32(&g_esrc[j], pol);
        int s1 = ld_el_s32(&g_esrc[j + 1], pol);
        int s2 = ld_el_s32(&g_esrc[j + 2], pol);
        int s3 = ld_el_s32(&g_esrc[j + 3], pol);
        uint2 u0 = ld_el_u2(&P2[(size_t)s0 * 16 + lane], pol);
        uint2 u1 = ld_el_u2(&P2[(size_t)s1 * 16 + lane], pol);
        uint2 u2 = ld_el_u2(&P2[(size_t)s2 * 16 + lane], pol);
        uint2 u3 = ld_el_u2(&P2[(size_t)s3 * 16 + lane], pol);
#pragma unroll
        for (int q = 0; q < 4; q++) {
            uint2 u = (q == 0) ? u0 : (q == 1) ? u1 : (q == 2) ? u2 : u3;
            float2 lo = __half22float2(*reinterpret_cast<const __half2*>(&u.x));
            float2 hi = __half22float2(*reinterpret_cast<const __half2*>(&u.y));
            acc.x += lo.x; acc.y += lo.y; acc.z += hi.x; acc.w += hi.y;
        }
    }
    for (; j < end; j++) {
        int s = ld_el_s32(&g_esrc[j], pol);
        uint2 u = ld_el_u2(&P2[(size_t)s * 16 + lane], pol);
        float2 lo = __half22float2(*reinterpret_cast<const __half2*>(&u.x));
        float2 hi = __half22float2(*reinterpret_cast<const __half2*>(&u.y));
        acc.x += lo.x; acc.y += lo.y; acc.z += hi.x; acc.w += hi.y;
    }
    return acc;
}

__device__ __forceinline__ float4 make_h(float4 acc, float4 b, float4 r) {
    float4 h;
    h.x = fmaxf(acc.x + b.x, 0.f) + r.x;
    h.y = fmaxf(acc.y + b.y, 0.f) + r.y;
    h.z = fmaxf(acc.z + b.z, 0.f) + r.z;
    h.w = fmaxf(acc.w + b.w, 0.f) + r.w;
    return h;
}

// ---------------- agg for layers 0,1: writes H = relu(acc+gb)+R ----------------
__global__ void agg_h(const float* __restrict__ gb) {
    unsigned tid = blockIdx.x * 256u + threadIdx.x;
    unsigned n = tid >> 4;
    if (n >= NN) return;
    int lane = tid & 15;
    unsigned long long pol = mk_pol_last();
    float4 acc = gather_node(n, lane, pol);
    float4 b = *reinterpret_cast<const float4*>(&gb[lane * 4]);
    float4 r = __ldcs(&reinterpret_cast<const float4*>(g_R)[(size_t)n * 16 + lane]);
    __stcs(&reinterpret_cast<float4*>(g_H)[(size_t)n * 16 + lane], make_h(acc, b, r));
}

// ---------------- agg for layer 2 fused with sum-pool ----------------
__global__ void agg_pool(const float* __restrict__ gb, const int* __restrict__ gid) {
    unsigned tid = blockIdx.x * 256u + threadIdx.x;
    unsigned n = tid >> 4;
    if (n >= NN) return;
    int lane = tid & 15;
    unsigned long long pol = mk_pol_last();
    float4 acc = gather_node(n, lane, pol);
    float4 b = *reinterpret_cast<const float4*>(&gb[lane * 4]);
    float4 r = __ldcs(&reinterpret_cast<const float4*>(g_R)[(size_t)n * 16 + lane]);
    float4 h = make_h(acc, b, r);
    int g = __ldg(&gid[n]);
    red4(&g_GF[(size_t)g * 64 + lane * 4], h);
}

// ---------------- fused classifier MLP: logits = relu(GF@W1+b1)@W2+b2 ----------------
__global__ void mlp_kernel(const float* __restrict__ cW1, const float* __restrict__ cb1,
                           const float* __restrict__ cW2, const float* __restrict__ cb2,
                           float* __restrict__ out) {
    __shared__ float W1[64 * 128];
    __shared__ float W2[128 * 2];
    __shared__ float Hs[16][128];
    int t = threadIdx.x;
    for (int i = t; i < 64 * 128; i += 256) W1[i] = cW1[i];
    if (t < 256) W2[t] = cW2[t];
    __syncthreads();

    int oc = t & 127;
    int half = t >> 7;
    float bias = __ldg(&cb1[oc]);
#pragma unroll
    for (int i = 0; i < 8; i++) {
        int gi = half * 8 + i;
        int g = blockIdx.x * 16 + gi;
        const float* gf = &g_GF[(size_t)g * 64];
        float s = bias;
#pragma unroll 8
        for (int k = 0; k < 64; k++) s += __ldg(&gf[k]) * W1[k * 128 + oc];
        Hs[gi][oc] = fmaxf(s, 0.f);
    }
    __syncthreads();

    if (t < 32) {
        int gi = t >> 1, cls = t & 1;
        float s = __ldg(&cb2[cls]);
#pragma unroll 8
        for (int k = 0; k < 128; k++) s += Hs[gi][k] * W2[k * 2 + cls];
        out[(blockIdx.x * 16 + gi) * 2 + cls] = s;
    }
}

// ---------------- launch ----------------
extern "C" void kernel_launch(void* const* d_in, const int* in_sizes, int n_in,
                              void* d_out, int out_size) {
    const float* node_feats = (const float*)d_in[0];
    const int*   src        = (const int*)d_in[1];
    const int*   dst        = (const int*)d_in[2];
    const int*   gid        = (const int*)d_in[3];
    const float* gW[3] = {(const float*)d_in[4],  (const float*)d_in[8],  (const float*)d_in[12]};
    const float* gb[3] = {(const float*)d_in[5],  (const float*)d_in[9],  (const float*)d_in[13]};
    const float* rW[3] = {(const float*)d_in[6],  (const float*)d_in[10], (const float*)d_in[14]};
    const float* rb[3] = {(const float*)d_in[7],  (const float*)d_in[11], (const float*)d_in[15]};
    const float* cW1 = (const float*)d_in[16];
    const float* cb1 = (const float*)d_in[17];
    const float* cW2 = (const float*)d_in[18];
    const float* cb2 = (const float*)d_in[19];
    float* out = (float*)d_out;

    float* gfp; cudaGetSymbolAddress((void**)&gfp, g_GF);

    const int E4_BLOCKS  = (NE / 4 + 255) / 256;  // 7813
    const int AGG_BLOCKS = (NN * 16) / 256;       // 31250
    const int ZM_BLOCKS  = (NN + 255) / 256;
    const int DSM_L0     = (2 * 80 * 64 + 32 * 84) * 4;   // 51712 B

    cudaStream_t s2 = g_aux.s;

    // fork: CSR build + zeroing on side stream, layer-0 GEMM on main stream
    cudaEventRecord(g_aux.eFork, 0);
    cudaStreamWaitEvent(s2, g_aux.eFork, 0);

    zero_misc_kernel<<<ZM_BLOCKS, 256, 0, s2>>>(gfp);
    hist_kernel<<<E4_BLOCKS, 256, 0, s2>>>((const int4*)dst);
    scan1_kernel<<<NB, 256, 0, s2>>>();
    scan23_kernel<<<NB, 256, 0, s2>>>();
    scatter_kernel<<<E4_BLOCKS, 256, 0, s2>>>((const int4*)src, (const int4*)dst);

    gemm_l0<<<GRID_L0, 256, DSM_L0>>>(node_feats, gW[0], rW[0], rb[0]);

    // join
    cudaEventRecord(g_aux.eJoin, s2);
    cudaStreamWaitEvent(0, g_aux.eJoin, 0);

    // layer 0 agg -> H
    agg_h<<<AGG_BLOCKS, 256>>>(gb[0]);
    // layer 1
    gemm64<<<GRID_64, 256>>>(gW[1], rW[1], rb[1]);
    agg_h<<<AGG_BLOCKS, 256>>>(gb[1]);
    // layer 2 (agg fused with pool)
    gemm64<<<GRID_64, 256>>>(gW[2], rW[2], rb[2]);
    agg_pool<<<AGG_BLOCKS, 256>>>(gb[2], gid);

    // fused classifier
    mlp_kernel<<<NG / 16, 256>>>(cW1, cb1, cW2, cb2, out);
}